// round 14
// baseline (speedup 1.0000x reference)
#include <cuda_runtime.h>
#include <math.h>

#define MEL_TOT (32*512*80)
#define NB 148
#define NT 512
#define GT (NB*NT)

typedef unsigned long long u64;

// ---------------- static device scratch ----------------
__device__ __align__(16) float g_tgtT[512*80*32];            // [t][k][b]
__device__ __align__(16) float g_pre1T[(size_t)512*256*32];  // [t][c][b]
__device__ __align__(16) float g_pre2T[(size_t)512*256*32];  // [t][c][b]
__device__ __align__(16) float g_Mt[512*128];                // [k][d]
__device__ __align__(16) float g_peT[(size_t)32*128*512];    // [b][d][t]
__device__ __align__(16) float g_C1[128*32], g_C2[128*32];   // [d][k] padded to 32
__device__ __align__(16) float g_WTa[(size_t)1792*4096];     // attn weights k-major [k][n]
__device__ __align__(16) float g_WTd[(size_t)2560*4096];     // dec  weights k-major [k][n]
__device__ __align__(16) float g_QwT[1024*128];              // [j][d]
__device__ __align__(16) float g_partA2[(size_t)8*64*32*64]; // [ks][ntile][b][n]
__device__ __align__(16) float g_partD2[(size_t)8*64*32*64];
__device__ __align__(16) float g_qP2[32*8*128];              // [b][chunk][d]
__device__ __align__(16) float g_ahT[1024*32], g_acT[1024*32]; // [j][b]
__device__ __align__(16) float g_dhT[1024*32], g_dcT[1024*32];
__device__ __align__(16) float g_dhB[32*1024];               // [b][j]
__device__ __align__(16) float g_ctxT[512*32];               // [e][b]
__device__ __align__(16) float g_ctxB[32*512];               // [b][e]
__device__ __align__(16) float g_ctxP[4*512*32];             // [tile][e][b]
__device__ __align__(16) float g_m[4*32], g_s[4*32];         // [tile][b]
__device__ __align__(16) float g_aw[32*512], g_aws[32*512], g_energy[32*512];
__device__ unsigned g_arrive, g_gen;

__device__ __forceinline__ float sig_(float x){
    x = fminf(fmaxf(x, -30.f), 30.f);
    return __fdividef(1.f, 1.f + __expf(-x));
}
__device__ __forceinline__ float tanh_(float x){
    float cx = fminf(fmaxf(x, -15.f), 15.f);
    float e2 = __expf(2.f*cx);
    return __fdividef(e2 - 1.f, e2 + 1.f);
}

// packed fp32x2 FMA (sm_103a FFMA2) — bitwise-identical to 2 scalar fp32 FMAs
__device__ __forceinline__ u64 ffma2(u64 a, u64 b, u64 c){
    u64 d;
    asm("fma.rn.f32x2 %0, %1, %2, %3;" : "=l"(d) : "l"(a), "l"(b), "l"(c));
    return d;
}

// ---------------- prep A: transposes + M^T + C1/C2 + weight k-major + QwT ----------------
__global__ void kprepA(const float* __restrict__ tgt, const float* __restrict__ Mw,
                       const float* __restrict__ Lw, const float* __restrict__ convw,
                       const float* __restrict__ awih, const float* __restrict__ awhh,
                       const float* __restrict__ dwih, const float* __restrict__ dwhh,
                       const float* __restrict__ Qw){
    __shared__ float tile[32][33];
    int bx = blockIdx.x;
    int tx = threadIdx.x & 31, ty = threadIdx.x >> 5;   // 256 threads: 32x8
    if (bx < 5120){
        int idx = bx*256 + threadIdx.x;
        if (idx < 32*512*80){
            int b = idx/(512*80); int r = idx - b*512*80; int t = r/80; int k = r - t*80;
            g_tgtT[((size_t)t*80+k)*32+b] = (t==0) ? 0.f : __ldcs(tgt + idx - 80);
        }
    } else if (bx < 5376){
        int idx = (bx-5120)*256 + threadIdx.x;     // 65536
        int d = idx >> 9, k = idx & 511;
        g_Mt[k*128+d] = Mw[idx];
    } else if (bx < 5392){
        int idx = (bx-5376)*256 + threadIdx.x;     // 4096
        int d = idx >> 5, k = idx & 31;
        float c1 = 0.f, c2 = 0.f;
        if (k < 31){
            for (int f = 0; f < 32; f++){
                float lw = Lw[d*32+f];
                c1 += lw*convw[f*62+k];
                c2 += lw*convw[f*62+31+k];
            }
        }
        g_C1[idx] = c1; g_C2[idx] = c2;
    } else if (bx < 12560){
        int b2 = bx - 5392;                        // attn: 56 k-tiles x 128 n-tiles
        int kt = b2 % 56, ntb = b2 / 56;
        int k0 = kt*32, n0 = ntb*32;
        #pragma unroll
        for (int i = 0; i < 32; i += 8){
            int n = n0 + ty + i, k = k0 + tx;
            float v = (k < 768) ? awih[(size_t)n*768 + k] : awhh[(size_t)n*1024 + k - 768];
            tile[ty+i][tx] = v;
        }
        __syncthreads();
        #pragma unroll
        for (int i = 0; i < 32; i += 8)
            g_WTa[(size_t)(k0 + ty + i)*4096 + n0 + tx] = tile[tx][ty+i];
    } else if (bx < 22800){
        int b2 = bx - 12560;                       // dec: 80 k-tiles x 128 n-tiles
        int kt = b2 % 80, ntb = b2 / 80;
        int k0 = kt*32, n0 = ntb*32;
        #pragma unroll
        for (int i = 0; i < 32; i += 8){
            int n = n0 + ty + i, k = k0 + tx;
            float v = (k < 1536) ? dwih[(size_t)n*1536 + k] : dwhh[(size_t)n*1024 + k - 1536];
            tile[ty+i][tx] = v;
        }
        __syncthreads();
        #pragma unroll
        for (int i = 0; i < 32; i += 8)
            g_WTd[(size_t)(k0 + ty + i)*4096 + n0 + tx] = tile[tx][ty+i];
    } else {
        int b2 = bx - 22800;                       // 128: Qw[128][1024] -> QwT[1024][128]
        int jt = b2 >> 2, dt = b2 & 3;
        int j0 = jt*32, d0 = dt*32;
        #pragma unroll
        for (int i = 0; i < 32; i += 8)
            tile[ty+i][tx] = Qw[(size_t)(d0 + ty + i)*1024 + j0 + tx];
        __syncthreads();
        #pragma unroll
        for (int i = 0; i < 32; i += 8)
            g_QwT[(size_t)(j0 + ty + i)*128 + d0 + tx] = tile[tx][ty+i];
    }
}

// ---------------- prep B: prenet layer 1 ----------------
__global__ void kprepB(const float* __restrict__ w1, const float* __restrict__ b1){
    int gw = blockIdx.x*8 + (threadIdx.x >> 5);
    int lane = threadIdx.x & 31;
    int t = gw >> 8, c = gw & 255;
    float acc = b1[c];
    const float4* w4 = (const float4*)(w1 + c*80);
    #pragma unroll
    for (int k = 0; k < 80; k += 4){
        float4 wv = __ldg(&w4[k >> 2]);
        const float* xp = g_tgtT + ((size_t)t*80 + k)*32 + lane;
        acc += wv.x*xp[0] + wv.y*xp[32] + wv.z*xp[64] + wv.w*xp[96];
    }
    g_pre1T[((size_t)t*256 + c)*32 + lane] = fmaxf(acc, 0.f);
}

// ---------------- prep C: prenet layer 2 + processed_enc (transposed) ----------------
__global__ void kprepC(const float* __restrict__ w2, const float* __restrict__ b2,
                       const float* __restrict__ enc){
    if (blockIdx.x < 16384){
        int gw = blockIdx.x*8 + (threadIdx.x >> 5);
        int lane = threadIdx.x & 31;
        int t = gw >> 8, c = gw & 255;
        float acc = b2[c];
        const float4* w4 = (const float4*)(w2 + c*256);
        #pragma unroll 4
        for (int k = 0; k < 256; k += 4){
            float4 wv = __ldg(&w4[k >> 2]);
            const float* xp = g_pre1T + ((size_t)t*256 + k)*32 + lane;
            acc += wv.x*xp[0] + wv.y*xp[32] + wv.z*xp[64] + wv.w*xp[96];
        }
        g_pre2T[((size_t)t*256 + c)*32 + lane] = fmaxf(acc, 0.f);
    } else {
        __shared__ float es[1024];
        int pb2 = blockIdx.x - 16384;               // 8192 blocks, 2 bt each
        int half = threadIdx.x >> 7, tid2 = threadIdx.x & 127;
        int bt = pb2*2 + half;
        float* esh = es + half*512;
        const float* ep = enc + (size_t)bt*512;
        for (int i = tid2; i < 512; i += 128) esh[i] = __ldg(ep + i);
        __syncthreads();
        float acc = 0.f;
        #pragma unroll 4
        for (int k = 0; k < 512; k += 4){
            const float* mp = g_Mt + (size_t)k*128 + tid2;
            acc += esh[k]*mp[0] + esh[k+1]*mp[128] + esh[k+2]*mp[256] + esh[k+3]*mp[384];
        }
        int b = bt >> 9, t = bt & 511;
        g_peT[(size_t)b*65536 + tid2*512 + t] = acc;   // [b][d][t]
    }
}

// ---------------- grid barrier ----------------
__device__ __forceinline__ void gridbar(){
    __syncthreads();
    if (threadIdx.x == 0){
        unsigned gen = *((volatile unsigned*)&g_gen);
        __threadfence();
        unsigned prev = atomicAdd(&g_arrive, 1u);
        if (prev == NB - 1){
            g_arrive = 0;
            __threadfence();
            atomicAdd(&g_gen, 1u);
        } else {
            while (*((volatile unsigned*)&g_gen) == gen) __nanosleep(32);
        }
        __threadfence();
    }
    __syncthreads();
}

// ---------------- register-tiled GEMV core with weight prefetch ----------------
// warp tile 64n x 32b; thread 8n x 8b; weights k-major; x splatted (v,v) in smem
// (xs row = 96 floats: 4 b-groups x 24-float stride, conflict-free LDS.128).
__device__ __forceinline__ void gemm_core(u64 acc[32], const float* __restrict__ WT,
        const float* __restrict__ xs, int k0, int ntile, int lane, int KSL)
{
    int ng = lane >> 2, bg = lane & 3;
    const float* wb = WT + (size_t)k0*4096 + ntile*64 + ng*8;
    const float* xb = xs + bg*24;
    #pragma unroll
    for (int i = 0; i < 32; i++) acc[i] = 0ull;
    ulonglong2 wA = *(const ulonglong2*)(wb);
    ulonglong2 wB = *(const ulonglong2*)(wb + 4);
    #pragma unroll 2
    for (int kl = 0; kl < KSL; kl++){
        int kn = (kl + 1 < KSL) ? kl + 1 : kl;
        ulonglong2 wA2 = *(const ulonglong2*)(wb + (size_t)kn*4096);
        ulonglong2 wB2 = *(const ulonglong2*)(wb + (size_t)kn*4096 + 4);
        const float* xr = xb + kl*96;
        ulonglong2 xA = *(const ulonglong2*)(xr);
        ulonglong2 xB = *(const ulonglong2*)(xr + 4);
        ulonglong2 xC = *(const ulonglong2*)(xr + 8);
        ulonglong2 xD = *(const ulonglong2*)(xr + 12);
        u64 xv[8] = {xA.x, xA.y, xB.x, xB.y, xC.x, xC.y, xD.x, xD.y};
        #pragma unroll
        for (int j = 0; j < 8; j++){
            acc[j]      = ffma2(wA.x, xv[j], acc[j]);
            acc[8 + j]  = ffma2(wA.y, xv[j], acc[8 + j]);
            acc[16 + j] = ffma2(wB.x, xv[j], acc[16 + j]);
            acc[24 + j] = ffma2(wB.y, xv[j], acc[24 + j]);
        }
        wA = wA2; wB = wB2;
    }
}

// in-block 4-way k-reduce via smem, coalesced global write of 8-ks partials
__device__ __forceinline__ void gemm_reduce_write(float* __restrict__ sh, u64 acc[32],
        float* __restrict__ gpart, int ngrp, int ksM, int wid, int lane)
{
    __syncthreads();                       // xs fully consumed
    {
        float* rp = sh + wid*2176 + lane*68;
        #pragma unroll
        for (int j = 0; j < 8; j++){
            #pragma unroll
            for (int np = 0; np < 4; np++)
                *(u64*)(rp + j*8 + np*2) = acc[np*8 + j];
        }
    }
    __syncthreads();
    if (wid < 4){
        int nt = ngrp*4 + wid;
        float* outp = gpart + (((size_t)ksM*64 + nt)*32)*64;
        int ngr = lane >> 2, npr = lane & 3;
        for (int b = 0; b < 32; b++){
            int bg = b >> 3, j = b & 7;
            float2 s = make_float2(0.f, 0.f);
            #pragma unroll
            for (int r = 0; r < 4; r++){
                float2 v = *(float2*)(sh + (wid + r*4)*2176 + (ngr*4 + bg)*68 + j*8 + npr*2);
                s.x += v.x; s.y += v.y;
            }
            *(float2*)(outp + b*64 + lane*2) = s;
        }
    }
}

// sum the 8 k-split partials for output row n, batch b
__device__ __forceinline__ float part_sum(const float* __restrict__ gpart, int n, int b){
    int ntile = n >> 6, nin = n & 63;
    const float* p = gpart + ((size_t)ntile*32 + b)*64 + nin;
    float s = 0.f;
    #pragma unroll
    for (int ks = 0; ks < 8; ks++) s += p[(size_t)ks*131072];
    return s;
}

// ---------------- output projection (coalesced via dhB/ctxB) ----------------
__device__ __forceinline__ void proj_warps(int nwarp, int lw, int lane, int step,
        const float* __restrict__ pw, const float* __restrict__ pb, float* __restrict__ out){
    for (int o = lw; o < 2560; o += nwarp){
        int mrow = o >> 5, b = o & 31;
        float s = 0.f;
        const float4* w4 = (const float4*)(pw + (size_t)mrow*1536);
        const float4* h4 = (const float4*)(g_dhB + b*1024);
        #pragma unroll
        for (int it = 0; it < 8; it++){
            int j4 = it*32 + lane;
            float4 w = __ldg(&w4[j4]);
            float4 h = h4[j4];
            s += w.x*h.x + w.y*h.y + w.z*h.z + w.w*h.w;
        }
        const float4* c4 = (const float4*)(g_ctxB + b*512);
        #pragma unroll
        for (int it = 0; it < 4; it++){
            int j4 = it*32 + lane;
            float4 w = __ldg(&w4[256 + j4]);
            float4 c = c4[j4];
            s += w.x*c.x + w.y*c.y + w.z*c.z + w.w*c.w;
        }
        #pragma unroll
        for (int off = 16; off; off >>= 1) s += __shfl_down_sync(0xffffffffu, s, off);
        if (lane == 0) __stcs(&out[((size_t)b*512 + step)*80 + mrow], s + __ldg(pb + mrow));
    }
}

// ---------------- persistent decoder ----------------
__global__ void __launch_bounds__(NT, 1) k_persist(
    const float* __restrict__ enc,
    const float* __restrict__ Ww,
    const float* __restrict__ abih, const float* __restrict__ abhh,
    const float* __restrict__ dbih, const float* __restrict__ dbhh,
    const float* __restrict__ pw,   const float* __restrict__ pb,
    float* __restrict__ out)
{
    extern __shared__ float sh[];
    __shared__ float swg[128];
    const int tid  = threadIdx.x;
    const int bx   = blockIdx.x;
    const int gtid = bx*NT + tid;
    const int lane = tid & 31;
    const int wid  = tid >> 5;

    for (int i = gtid; i < 32768; i += GT){ g_ahT[i]=0.f; g_acT[i]=0.f; g_dhT[i]=0.f; g_dcT[i]=0.f; g_dhB[i]=0.f; }
    for (int i = gtid; i < 16384; i += GT){ g_ctxT[i]=0.f; g_ctxB[i]=0.f; g_aw[i]=0.f; g_aws[i]=0.f; }
    gridbar();

    for (int step = 0; step < 512; step++){
        // ==== P1: attn GEMM (0..127) | dec cell(step-1) (128..147) ====
        if (bx < 128){
            const int KSL = 56, KSB = 224;
            int ngrp = bx >> 3, ksM = bx & 7;
            int k0b = ksM*KSB;
            for (int idx = tid; idx < KSB*32; idx += NT){
                int kl = idx >> 5, b = idx & 31, gk = k0b + kl;
                float v;
                if (gk < 256)      v = __ldcs(&g_pre2T[((size_t)step*256 + gk)*32 + b]);
                else if (gk < 768) v = g_ctxT[(gk-256)*32 + b];
                else               v = g_ahT[(gk-768)*32 + b];
                *(float2*)(sh + kl*96 + (b>>3)*24 + (b&7)*2) = make_float2(v, v);
            }
            __syncthreads();
            int ntile = ngrp*4 + (wid & 3);
            int ksub = wid >> 2;
            u64 acc[32];
            gemm_core(acc, g_WTa, sh + ksub*KSL*96, k0b + ksub*KSL, ntile, lane, KSL);
            gemm_reduce_write(sh, acc, g_partA2, ngrp, ksM, wid, lane);
        } else if (step > 0){
            for (int o = (bx-128)*NT + tid; o < 32768; o += 20*NT){
                int b = o >> 10, j = o & 1023;
                float gi = dbih[j]      + dbhh[j]      + part_sum(g_partD2, j, b);
                float gf = dbih[1024+j] + dbhh[1024+j] + part_sum(g_partD2, 1024+j, b);
                float gg = dbih[2048+j] + dbhh[2048+j] + part_sum(g_partD2, 2048+j, b);
                float go = dbih[3072+j] + dbhh[3072+j] + part_sum(g_partD2, 3072+j, b);
                float c  = g_dcT[j*32+b];
                float c2 = sig_(gf)*c + sig_(gi)*tanh_(gg);
                float h  = sig_(go)*tanh_(c2);
                g_dcT[j*32+b] = c2;
                g_dhT[j*32+b] = h;
                g_dhB[b*1024+j] = h;
            }
        }
        gridbar();

        // ==== P2: attn cell + q partials (0..63) | proj(step-1) (64..147) ====
        if (bx < 64){
            int b = bx >> 1, jhalf = bx & 1;
            int j = (jhalf << 9) + tid;
            float gi = abih[j]      + abhh[j]      + part_sum(g_partA2, j, b);
            float gf = abih[1024+j] + abhh[1024+j] + part_sum(g_partA2, 1024+j, b);
            float gg = abih[2048+j] + abhh[2048+j] + part_sum(g_partA2, 2048+j, b);
            float go = abih[3072+j] + abhh[3072+j] + part_sum(g_partA2, 3072+j, b);
            float c  = g_acT[j*32+b];
            float c2 = sig_(gf)*c + sig_(gi)*tanh_(gg);
            float h  = sig_(go)*tanh_(c2);
            g_acT[j*32+b] = c2;
            g_ahT[j*32+b] = h;
            sh[tid] = h;
            __syncthreads();
            int d = tid & 127, quarter = tid >> 7;
            const float* qt = g_QwT + ((size_t)(jhalf*512 + quarter*128))*128 + d;
            const float* hp = sh + quarter*128;
            float s = 0.f;
            #pragma unroll 8
            for (int jj = 0; jj < 128; jj++) s += qt[(size_t)jj*128] * hp[jj];
            g_qP2[(b*8 + jhalf*4 + quarter)*128 + d] = s;
        } else if (step > 0){
            int lw = (bx - 64)*16 + wid;   // 0..1343
            proj_warps(1344, lw, lane, step-1, pw, pb, out);
        }
        gridbar();

        // ==== P3: energies + softmax partials + ctx partials (0..127) ====
        if (bx < 128){
            int b = bx >> 2, tile = bx & 3, t0 = tile*128;
            for (int i = tid; i < 4096; i += NT){
                int d = i >> 5, k = i & 31;
                sh[d*40 + k]        = g_C1[i];
                sh[5120 + d*40 + k] = g_C2[i];
            }
            if (tid < 128){
                float s = 0.f;
                #pragma unroll
                for (int c = 0; c < 8; c++) s += g_qP2[(b*8 + c)*128 + tid];
                sh[10752 + tid] = s;
                sh[10880 + tid] = __ldg(Ww + tid);
            }
            for (int i = tid; i < 158; i += NT){
                int gi = t0 - 15 + i;
                bool ok = (gi >= 0 && gi < 512);
                sh[11008 + i] = ok ? g_aw [b*512 + gi] : 0.f;
                sh[11168 + i] = ok ? g_aws[b*512 + gi] : 0.f;
            }
            __syncthreads();
            int tt = tid >> 2, sub = tid & 3, t = t0 + tt;
            float ar[32], asr[32];
            #pragma unroll
            for (int k = 0; k < 31; k++){ ar[k] = sh[11008 + tt + k]; asr[k] = sh[11168 + tt + k]; }
            ar[31] = 0.f; asr[31] = 0.f;
            const float* pep = g_peT + (size_t)b*65536 + t;
            float e = 0.f;
            #pragma unroll 1
            for (int dd = 0; dd < 32; dd++){
                int d = dd*4 + sub;
                float l = sh[10752 + d] + __ldg(pep + (size_t)d*512);
                const float4* c14 = (const float4*)(sh + d*40);
                const float4* c24 = (const float4*)(sh + 5120 + d*40);
                #pragma unroll
                for (int i = 0; i < 8; i++){
                    float4 w1 = c14[i], w2 = c24[i];
                    l += ar[i*4]*w1.x + ar[i*4+1]*w1.y + ar[i*4+2]*w1.z + ar[i*4+3]*w1.w;
                    l += asr[i*4]*w2.x + asr[i*4+1]*w2.y + asr[i*4+2]*w2.z + asr[i*4+3]*w2.w;
                }
                e += sh[10880 + d]*tanh_(l);
            }
            e += __shfl_xor_sync(0xffffffffu, e, 1);
            e += __shfl_xor_sync(0xffffffffu, e, 2);
            if (sub == 0){ sh[11328 + tt] = e; g_energy[b*512 + t] = e; }
            __syncthreads();
            if (tid < 128) sh[10240 + tid] = sh[11328 + tid];
            __syncthreads();
            if (tid < 64) sh[10240+tid] = fmaxf(sh[10240+tid], sh[10240+tid+64]);
            __syncthreads();
            if (tid < 32){
                float m = fmaxf(sh[10240+tid], sh[10240+tid+32]);
                #pragma unroll
                for (int o = 16; o; o >>= 1) m = fmaxf(m, __shfl_down_sync(0xffffffffu, m, o));
                if (tid == 0) sh[10240] = m;
            }
            __syncthreads();
            float mi = sh[10240];
            __syncthreads();
            if (tid < 128){
                float p = __expf(sh[11328 + tid] - mi);
                sh[11456 + tid] = p;
                sh[11584 + tid] = p;
            }
            __syncthreads();
            if (tid < 64) sh[11584+tid] += sh[11584+tid+64];
            __syncthreads();
            if (tid < 32){
                float s = sh[11584+tid] + sh[11584+tid+32];
                #pragma unroll
                for (int o = 16; o; o >>= 1) s += __shfl_down_sync(0xffffffffu, s, o);
                if (tid == 0){ g_m[tile*32 + b] = mi; g_s[tile*32 + b] = s; }
            }
            __syncthreads();
            // ctx partial: enc is now L2-RESIDENT (hot set ~121MB < 126MB after
            // the R12 partials diet) — cached loads instead of evict-first stream.
            float acc = 0.f;
            const float* ep = enc + (size_t)b*262144 + (size_t)t0*512 + tid;
            #pragma unroll 16
            for (int t2 = 0; t2 < 128; t2++) acc += sh[11456 + t2]*__ldg(ep + (size_t)t2*512);
            g_ctxP[((size_t)tile*512 + tid)*32 + b] = acc;
        }
        gridbar();

        // ==== P4: dec GEMM + inline ctx reduce (0..127) | finalize (128..147) ====
        if (bx < 128){
            if (tid < 32){
                int b = tid;
                float m0=g_m[b], m1=g_m[32+b], m2=g_m[64+b], m3=g_m[96+b];
                float M = fmaxf(fmaxf(m0,m1), fmaxf(m2,m3));
                float e0=__expf(m0-M), e1=__expf(m1-M), e2=__expf(m2-M), e3=__expf(m3-M);
                float S = g_s[b]*e0 + g_s[32+b]*e1 + g_s[64+b]*e2 + g_s[96+b]*e3;
                float inv = __fdividef(1.f, S);
                swg[b]=e0*inv; swg[32+b]=e1*inv; swg[64+b]=e2*inv; swg[96+b]=e3*inv;
            }
            __syncthreads();
            const int KSL = 80, KSB = 320;
            int ngrp = bx >> 3, ksM = bx & 7;
            int k0b = ksM*KSB;
            for (int idx = tid; idx < KSB*32; idx += NT){
                int kl = idx >> 5, b = idx & 31, gk = k0b + kl;
                float v;
                if (gk < 1024)      v = g_ahT[gk*32 + b];
                else if (gk < 1536){
                    int o = (gk-1024)*32 + b;
                    v = swg[b]*g_ctxP[o] + swg[32+b]*g_ctxP[16384+o]
                      + swg[64+b]*g_ctxP[32768+o] + swg[96+b]*g_ctxP[49152+o];
                } else               v = g_dhT[(gk-1536)*32 + b];
                *(float2*)(sh + kl*96 + (b>>3)*24 + (b&7)*2) = make_float2(v, v);
            }
            __syncthreads();
            int ntile = ngrp*4 + (wid & 3);
            int ksub = wid >> 2;
            u64 acc[32];
            gemm_core(acc, g_WTd, sh + ksub*KSL*96, k0b + ksub*KSL, ntile, lane, KSL);
            gemm_reduce_write(sh, acc, g_partD2, ngrp, ksM, wid, lane);
        } else {
            for (int b = bx - 128; b < 32; b += 20){
                float m0=g_m[b], m1=g_m[32+b], m2=g_m[64+b], m3=g_m[96+b];
                float M = fmaxf(fmaxf(m0,m1), fmaxf(m2,m3));
                float e0=__expf(m0-M), e1=__expf(m1-M), e2=__expf(m2-M), e3=__expf(m3-M);
                float S = g_s[b]*e0 + g_s[32+b]*e1 + g_s[64+b]*e2 + g_s[96+b]*e3;
                float inv = __fdividef(1.f, S);
                float w0=e0*inv, w1=e1*inv, w2=e2*inv, w3=e3*inv;
                float a = __expf(g_energy[b*512 + tid] - M)*inv;
                g_aw[b*512 + tid] = a;
                g_aws[b*512 + tid] += a;
                __stcs(&out[MEL_TOT + ((size_t)b*512 + step)*512 + tid], a);
                int o = tid*32 + b;
                float v = w0*g_ctxP[o] + w1*g_ctxP[16384+o] + w2*g_ctxP[32768+o] + w3*g_ctxP[49152+o];
                g_ctxT[o] = v;
                g_ctxB[b*512 + tid] = v;
            }
        }
        gridbar();
    }

    // ==== epilogue: dec cell for step 511, then proj(511) ====
    for (int o = gtid; o < 32768; o += GT){
        int b = o >> 10, j = o & 1023;
        float gi = dbih[j]      + dbhh[j]      + part_sum(g_partD2, j, b);
        float gf = dbih[1024+j] + dbhh[1024+j] + part_sum(g_partD2, 1024+j, b);
        float gg = dbih[2048+j] + dbhh[2048+j] + part_sum(g_partD2, 2048+j, b);
        float go = dbih[3072+j] + dbhh[3072+j] + part_sum(g_partD2, 3072+j, b);
        float c  = g_dcT[j*32+b];
        float c2 = sig_(gf)*c + sig_(gi)*tanh_(gg);
        float h  = sig_(go)*tanh_(c2);
        g_dhB[b*1024+j] = h;
    }
    gridbar();
    proj_warps(NB*16, gtid >> 5, lane, 511, pw, pb, out);
}

// ---------------- launch ----------------
extern "C" void kernel_launch(void* const* d_in, const int* in_sizes, int n_in,
                              void* d_out, int out_size){
    const float* enc   = (const float*)d_in[0];
    const float* tgt   = (const float*)d_in[1];
    const float* w1    = (const float*)d_in[2];
    const float* b1    = (const float*)d_in[3];
    const float* w2    = (const float*)d_in[4];
    const float* b2    = (const float*)d_in[5];
    const float* Mw    = (const float*)d_in[6];
    const float* Qw    = (const float*)d_in[7];
    const float* Ww    = (const float*)d_in[8];
    const float* Lw    = (const float*)d_in[9];
    const float* convw = (const float*)d_in[10];
    const float* awih  = (const float*)d_in[11];
    const float* awhh  = (const float*)d_in[12];
    const float* abih  = (const float*)d_in[13];
    const float* abhh  = (const float*)d_in[14];
    const float* dwih  = (const float*)d_in[15];
    const float* dwhh  = (const float*)d_in[16];
    const float* dbih  = (const float*)d_in[17];
    const float* dbhh  = (const float*)d_in[18];
    const float* pw    = (const float*)d_in[19];
    const float* pb    = (const float*)d_in[20];
    float* out = (float*)d_out;

    kprepA<<<22928, 256>>>(tgt, Mw, Lw, convw, awih, awhh, dwih, dwhh, Qw);
    kprepB<<<16384, 256>>>(w1, b1);
    kprepC<<<24576, 256>>>(w2, b2, enc);

    cudaFuncSetAttribute(k_persist, cudaFuncAttributeMaxDynamicSharedMemorySize, 143360);
    k_persist<<<NB, NT, 143360>>>(enc, Ww,
                                  abih, abhh, dbih, dbhh, pw, pb, out);
}

// round 15
// speedup vs baseline: 1.0350x; 1.0350x over previous
#include <cuda_runtime.h>
#include <cuda_fp16.h>
#include <math.h>

#define MEL_TOT (32*512*80)
#define NB 148
#define NT 512
#define GT (NB*NT)

typedef unsigned long long u64;

// ---------------- static device scratch ----------------
__device__ __align__(16) float g_tgtT[512*80*32];            // [t][k][b]
__device__ __align__(16) float g_pre1T[(size_t)512*256*32];  // [t][c][b]
__device__ __align__(16) float g_pre2T[(size_t)512*256*32];  // [t][c][b]
__device__ __align__(16) float g_Mt[512*128];                // [k][d]
__device__ __align__(16) float g_peT[(size_t)32*128*512];    // [b][d][t]
__device__ __align__(16) __half2 g_encH[(size_t)32*512*256]; // [b][t][epair] fp16 copy
__device__ __align__(16) float g_C1[128*32], g_C2[128*32];   // [d][k] padded to 32
__device__ __align__(16) float g_WTa[(size_t)1792*4096];     // attn weights k-major [k][n]
__device__ __align__(16) float g_WTd[(size_t)2560*4096];     // dec  weights k-major [k][n]
__device__ __align__(16) float g_QwT[1024*128];              // [j][d]
__device__ __align__(16) float g_partA2[(size_t)8*64*32*64]; // [ks][ntile][b][n]
__device__ __align__(16) float g_partD2[(size_t)8*64*32*64];
__device__ __align__(16) float g_qP2[32*8*128];              // [b][chunk][d]
__device__ __align__(16) float g_ahT[1024*32], g_acT[1024*32]; // [j][b]
__device__ __align__(16) float g_dhT[1024*32], g_dcT[1024*32];
__device__ __align__(16) float g_dhB[32*1024];               // [b][j]
__device__ __align__(16) float g_ctxT[512*32];               // [e][b]
__device__ __align__(16) float g_ctxB[32*512];               // [b][e]
__device__ __align__(16) float g_ctxP[4*512*32];             // [tile][e][b]
__device__ __align__(16) float g_m[4*32], g_s[4*32];         // [tile][b]
__device__ __align__(16) float g_aw[32*512], g_aws[32*512], g_energy[32*512];
__device__ unsigned g_arrive, g_gen;

__device__ __forceinline__ float sig_(float x){
    x = fminf(fmaxf(x, -30.f), 30.f);
    return __fdividef(1.f, 1.f + __expf(-x));
}
__device__ __forceinline__ float tanh_(float x){
    float cx = fminf(fmaxf(x, -15.f), 15.f);
    float e2 = __expf(2.f*cx);
    return __fdividef(e2 - 1.f, e2 + 1.f);
}

// packed fp32x2 FMA (sm_103a FFMA2) — bitwise-identical to 2 scalar fp32 FMAs
__device__ __forceinline__ u64 ffma2(u64 a, u64 b, u64 c){
    u64 d;
    asm("fma.rn.f32x2 %0, %1, %2, %3;" : "=l"(d) : "l"(a), "l"(b), "l"(c));
    return d;
}

// ---------------- prep A: transposes + M^T + C1/C2 + weight k-major + QwT ----------------
__global__ void kprepA(const float* __restrict__ tgt, const float* __restrict__ Mw,
                       const float* __restrict__ Lw, const float* __restrict__ convw,
                       const float* __restrict__ awih, const float* __restrict__ awhh,
                       const float* __restrict__ dwih, const float* __restrict__ dwhh,
                       const float* __restrict__ Qw){
    __shared__ float tile[32][33];
    int bx = blockIdx.x;
    int tx = threadIdx.x & 31, ty = threadIdx.x >> 5;   // 256 threads: 32x8
    if (bx < 5120){
        int idx = bx*256 + threadIdx.x;
        if (idx < 32*512*80){
            int b = idx/(512*80); int r = idx - b*512*80; int t = r/80; int k = r - t*80;
            g_tgtT[((size_t)t*80+k)*32+b] = (t==0) ? 0.f : __ldcs(tgt + idx - 80);
        }
    } else if (bx < 5376){
        int idx = (bx-5120)*256 + threadIdx.x;     // 65536
        int d = idx >> 9, k = idx & 511;
        g_Mt[k*128+d] = Mw[idx];
    } else if (bx < 5392){
        int idx = (bx-5376)*256 + threadIdx.x;     // 4096
        int d = idx >> 5, k = idx & 31;
        float c1 = 0.f, c2 = 0.f;
        if (k < 31){
            for (int f = 0; f < 32; f++){
                float lw = Lw[d*32+f];
                c1 += lw*convw[f*62+k];
                c2 += lw*convw[f*62+31+k];
            }
        }
        g_C1[idx] = c1; g_C2[idx] = c2;
    } else if (bx < 12560){
        int b2 = bx - 5392;                        // attn: 56 k-tiles x 128 n-tiles
        int kt = b2 % 56, ntb = b2 / 56;
        int k0 = kt*32, n0 = ntb*32;
        #pragma unroll
        for (int i = 0; i < 32; i += 8){
            int n = n0 + ty + i, k = k0 + tx;
            float v = (k < 768) ? awih[(size_t)n*768 + k] : awhh[(size_t)n*1024 + k - 768];
            tile[ty+i][tx] = v;
        }
        __syncthreads();
        #pragma unroll
        for (int i = 0; i < 32; i += 8)
            g_WTa[(size_t)(k0 + ty + i)*4096 + n0 + tx] = tile[tx][ty+i];
    } else if (bx < 22800){
        int b2 = bx - 12560;                       // dec: 80 k-tiles x 128 n-tiles
        int kt = b2 % 80, ntb = b2 / 80;
        int k0 = kt*32, n0 = ntb*32;
        #pragma unroll
        for (int i = 0; i < 32; i += 8){
            int n = n0 + ty + i, k = k0 + tx;
            float v = (k < 1536) ? dwih[(size_t)n*1536 + k] : dwhh[(size_t)n*1024 + k - 1536];
            tile[ty+i][tx] = v;
        }
        __syncthreads();
        #pragma unroll
        for (int i = 0; i < 32; i += 8)
            g_WTd[(size_t)(k0 + ty + i)*4096 + n0 + tx] = tile[tx][ty+i];
    } else {
        int b2 = bx - 22800;                       // 128: Qw[128][1024] -> QwT[1024][128]
        int jt = b2 >> 2, dt = b2 & 3;
        int j0 = jt*32, d0 = dt*32;
        #pragma unroll
        for (int i = 0; i < 32; i += 8)
            tile[ty+i][tx] = Qw[(size_t)(d0 + ty + i)*1024 + j0 + tx];
        __syncthreads();
        #pragma unroll
        for (int i = 0; i < 32; i += 8)
            g_QwT[(size_t)(j0 + ty + i)*128 + d0 + tx] = tile[tx][ty+i];
    }
}

// ---------------- prep B: prenet layer 1 ----------------
__global__ void kprepB(const float* __restrict__ w1, const float* __restrict__ b1){
    int gw = blockIdx.x*8 + (threadIdx.x >> 5);
    int lane = threadIdx.x & 31;
    int t = gw >> 8, c = gw & 255;
    float acc = b1[c];
    const float4* w4 = (const float4*)(w1 + c*80);
    #pragma unroll
    for (int k = 0; k < 80; k += 4){
        float4 wv = __ldg(&w4[k >> 2]);
        const float* xp = g_tgtT + ((size_t)t*80 + k)*32 + lane;
        acc += wv.x*xp[0] + wv.y*xp[32] + wv.z*xp[64] + wv.w*xp[96];
    }
    g_pre1T[((size_t)t*256 + c)*32 + lane] = fmaxf(acc, 0.f);
}

// ---------------- prep C: prenet layer 2 + processed_enc + fp16 enc copy ----------------
__global__ void kprepC(const float* __restrict__ w2, const float* __restrict__ b2,
                       const float* __restrict__ enc){
    if (blockIdx.x < 16384){
        int gw = blockIdx.x*8 + (threadIdx.x >> 5);
        int lane = threadIdx.x & 31;
        int t = gw >> 8, c = gw & 255;
        float acc = b2[c];
        const float4* w4 = (const float4*)(w2 + c*256);
        #pragma unroll 4
        for (int k = 0; k < 256; k += 4){
            float4 wv = __ldg(&w4[k >> 2]);
            const float* xp = g_pre1T + ((size_t)t*256 + k)*32 + lane;
            acc += wv.x*xp[0] + wv.y*xp[32] + wv.z*xp[64] + wv.w*xp[96];
        }
        g_pre2T[((size_t)t*256 + c)*32 + lane] = fmaxf(acc, 0.f);
    } else {
        __shared__ float es[1024];
        int pb2 = blockIdx.x - 16384;               // 8192 blocks, 2 bt each
        int half = threadIdx.x >> 7, tid2 = threadIdx.x & 127;
        int bt = pb2*2 + half;
        float* esh = es + half*512;
        const float* ep = enc + (size_t)bt*512;
        for (int i = tid2; i < 512; i += 128) esh[i] = __ldcs(ep + i);
        __syncthreads();
        // fp16 copy of this enc row (256 half2 per bt)
        for (int i = tid2; i < 256; i += 128)
            g_encH[(size_t)bt*256 + i] = __floats2half2_rn(esh[2*i], esh[2*i+1]);
        float acc = 0.f;
        #pragma unroll 4
        for (int k = 0; k < 512; k += 4){
            const float* mp = g_Mt + (size_t)k*128 + tid2;
            acc += esh[k]*mp[0] + esh[k+1]*mp[128] + esh[k+2]*mp[256] + esh[k+3]*mp[384];
        }
        int b = bt >> 9, t = bt & 511;
        g_peT[(size_t)b*65536 + tid2*512 + t] = acc;   // [b][d][t]
    }
}

// ---------------- grid barrier ----------------
__device__ __forceinline__ void gridbar(){
    __syncthreads();
    if (threadIdx.x == 0){
        unsigned gen = *((volatile unsigned*)&g_gen);
        __threadfence();
        unsigned prev = atomicAdd(&g_arrive, 1u);
        if (prev == NB - 1){
            g_arrive = 0;
            __threadfence();
            atomicAdd(&g_gen, 1u);
        } else {
            while (*((volatile unsigned*)&g_gen) == gen) __nanosleep(32);
        }
        __threadfence();
    }
    __syncthreads();
}

// ---------------- register-tiled GEMV core with weight prefetch ----------------
__device__ __forceinline__ void gemm_core(u64 acc[32], const float* __restrict__ WT,
        const float* __restrict__ xs, int k0, int ntile, int lane, int KSL)
{
    int ng = lane >> 2, bg = lane & 3;
    const float* wb = WT + (size_t)k0*4096 + ntile*64 + ng*8;
    const float* xb = xs + bg*24;
    #pragma unroll
    for (int i = 0; i < 32; i++) acc[i] = 0ull;
    ulonglong2 wA = *(const ulonglong2*)(wb);
    ulonglong2 wB = *(const ulonglong2*)(wb + 4);
    #pragma unroll 2
    for (int kl = 0; kl < KSL; kl++){
        int kn = (kl + 1 < KSL) ? kl + 1 : kl;
        ulonglong2 wA2 = *(const ulonglong2*)(wb + (size_t)kn*4096);
        ulonglong2 wB2 = *(const ulonglong2*)(wb + (size_t)kn*4096 + 4);
        const float* xr = xb + kl*96;
        ulonglong2 xA = *(const ulonglong2*)(xr);
        ulonglong2 xB = *(const ulonglong2*)(xr + 4);
        ulonglong2 xC = *(const ulonglong2*)(xr + 8);
        ulonglong2 xD = *(const ulonglong2*)(xr + 12);
        u64 xv[8] = {xA.x, xA.y, xB.x, xB.y, xC.x, xC.y, xD.x, xD.y};
        #pragma unroll
        for (int j = 0; j < 8; j++){
            acc[j]      = ffma2(wA.x, xv[j], acc[j]);
            acc[8 + j]  = ffma2(wA.y, xv[j], acc[8 + j]);
            acc[16 + j] = ffma2(wB.x, xv[j], acc[16 + j]);
            acc[24 + j] = ffma2(wB.y, xv[j], acc[24 + j]);
        }
        wA = wA2; wB = wB2;
    }
}

// in-block 4-way k-reduce via smem, coalesced global write of 8-ks partials
__device__ __forceinline__ void gemm_reduce_write(float* __restrict__ sh, u64 acc[32],
        float* __restrict__ gpart, int ngrp, int ksM, int wid, int lane)
{
    __syncthreads();                       // xs fully consumed
    {
        float* rp = sh + wid*2176 + lane*68;
        #pragma unroll
        for (int j = 0; j < 8; j++){
            #pragma unroll
            for (int np = 0; np < 4; np++)
                *(u64*)(rp + j*8 + np*2) = acc[np*8 + j];
        }
    }
    __syncthreads();
    if (wid < 4){
        int nt = ngrp*4 + wid;
        float* outp = gpart + (((size_t)ksM*64 + nt)*32)*64;
        int ngr = lane >> 2, npr = lane & 3;
        for (int b = 0; b < 32; b++){
            int bg = b >> 3, j = b & 7;
            float2 s = make_float2(0.f, 0.f);
            #pragma unroll
            for (int r = 0; r < 4; r++){
                float2 v = *(float2*)(sh + (wid + r*4)*2176 + (ngr*4 + bg)*68 + j*8 + npr*2);
                s.x += v.x; s.y += v.y;
            }
            *(float2*)(outp + b*64 + lane*2) = s;
        }
    }
}

// sum the 8 k-split partials for output row n, batch b
__device__ __forceinline__ float part_sum(const float* __restrict__ gpart, int n, int b){
    int ntile = n >> 6, nin = n & 63;
    const float* p = gpart + ((size_t)ntile*32 + b)*64 + nin;
    float s = 0.f;
    #pragma unroll
    for (int ks = 0; ks < 8; ks++) s += p[(size_t)ks*131072];
    return s;
}

// ---------------- output projection (coalesced via dhB/ctxB) ----------------
__device__ __forceinline__ void proj_warps(int nwarp, int lw, int lane, int step,
        const float* __restrict__ pw, const float* __restrict__ pb, float* __restrict__ out){
    for (int o = lw; o < 2560; o += nwarp){
        int mrow = o >> 5, b = o & 31;
        float s = 0.f;
        const float4* w4 = (const float4*)(pw + (size_t)mrow*1536);
        const float4* h4 = (const float4*)(g_dhB + b*1024);
        #pragma unroll
        for (int it = 0; it < 8; it++){
            int j4 = it*32 + lane;
            float4 w = __ldg(&w4[j4]);
            float4 h = h4[j4];
            s += w.x*h.x + w.y*h.y + w.z*h.z + w.w*h.w;
        }
        const float4* c4 = (const float4*)(g_ctxB + b*512);
        #pragma unroll
        for (int it = 0; it < 4; it++){
            int j4 = it*32 + lane;
            float4 w = __ldg(&w4[256 + j4]);
            float4 c = c4[j4];
            s += w.x*c.x + w.y*c.y + w.z*c.z + w.w*c.w;
        }
        #pragma unroll
        for (int off = 16; off; off >>= 1) s += __shfl_down_sync(0xffffffffu, s, off);
        if (lane == 0) __stcs(&out[((size_t)b*512 + step)*80 + mrow], s + __ldg(pb + mrow));
    }
}

// ---------------- persistent decoder ----------------
__global__ void __launch_bounds__(NT, 1) k_persist(
    const float* __restrict__ Ww,
    const float* __restrict__ abih, const float* __restrict__ abhh,
    const float* __restrict__ dbih, const float* __restrict__ dbhh,
    const float* __restrict__ pw,   const float* __restrict__ pb,
    float* __restrict__ out)
{
    extern __shared__ float sh[];
    __shared__ float swg[128];
    const int tid  = threadIdx.x;
    const int bx   = blockIdx.x;
    const int gtid = bx*NT + tid;
    const int lane = tid & 31;
    const int wid  = tid >> 5;

    for (int i = gtid; i < 32768; i += GT){ g_ahT[i]=0.f; g_acT[i]=0.f; g_dhT[i]=0.f; g_dcT[i]=0.f; g_dhB[i]=0.f; }
    for (int i = gtid; i < 16384; i += GT){ g_ctxT[i]=0.f; g_ctxB[i]=0.f; g_aw[i]=0.f; g_aws[i]=0.f; }
    gridbar();

    for (int step = 0; step < 512; step++){
        // ==== P1: attn GEMM (0..127) | dec cell(step-1) (128..147) ====
        if (bx < 128){
            const int KSL = 56, KSB = 224;
            int ngrp = bx >> 3, ksM = bx & 7;
            int k0b = ksM*KSB;
            for (int idx = tid; idx < KSB*32; idx += NT){
                int kl = idx >> 5, b = idx & 31, gk = k0b + kl;
                float v;
                if (gk < 256)      v = __ldcs(&g_pre2T[((size_t)step*256 + gk)*32 + b]);
                else if (gk < 768) v = g_ctxT[(gk-256)*32 + b];
                else               v = g_ahT[(gk-768)*32 + b];
                *(float2*)(sh + kl*96 + (b>>3)*24 + (b&7)*2) = make_float2(v, v);
            }
            __syncthreads();
            int ntile = ngrp*4 + (wid & 3);
            int ksub = wid >> 2;
            u64 acc[32];
            gemm_core(acc, g_WTa, sh + ksub*KSL*96, k0b + ksub*KSL, ntile, lane, KSL);
            gemm_reduce_write(sh, acc, g_partA2, ngrp, ksM, wid, lane);
        } else if (step > 0){
            for (int o = (bx-128)*NT + tid; o < 32768; o += 20*NT){
                int b = o >> 10, j = o & 1023;
                float gi = dbih[j]      + dbhh[j]      + part_sum(g_partD2, j, b);
                float gf = dbih[1024+j] + dbhh[1024+j] + part_sum(g_partD2, 1024+j, b);
                float gg = dbih[2048+j] + dbhh[2048+j] + part_sum(g_partD2, 2048+j, b);
                float go = dbih[3072+j] + dbhh[3072+j] + part_sum(g_partD2, 3072+j, b);
                float c  = g_dcT[j*32+b];
                float c2 = sig_(gf)*c + sig_(gi)*tanh_(gg);
                float h  = sig_(go)*tanh_(c2);
                g_dcT[j*32+b] = c2;
                g_dhT[j*32+b] = h;
                g_dhB[b*1024+j] = h;
            }
        }
        gridbar();

        // ==== P2: attn cell + q partials (0..63) | proj(step-1) (64..147) ====
        if (bx < 64){
            int b = bx >> 1, jhalf = bx & 1;
            int j = (jhalf << 9) + tid;
            float gi = abih[j]      + abhh[j]      + part_sum(g_partA2, j, b);
            float gf = abih[1024+j] + abhh[1024+j] + part_sum(g_partA2, 1024+j, b);
            float gg = abih[2048+j] + abhh[2048+j] + part_sum(g_partA2, 2048+j, b);
            float go = abih[3072+j] + abhh[3072+j] + part_sum(g_partA2, 3072+j, b);
            float c  = g_acT[j*32+b];
            float c2 = sig_(gf)*c + sig_(gi)*tanh_(gg);
            float h  = sig_(go)*tanh_(c2);
            g_acT[j*32+b] = c2;
            g_ahT[j*32+b] = h;
            sh[tid] = h;
            __syncthreads();
            int d = tid & 127, quarter = tid >> 7;
            const float* qt = g_QwT + ((size_t)(jhalf*512 + quarter*128))*128 + d;
            const float* hp = sh + quarter*128;
            float s = 0.f;
            #pragma unroll 8
            for (int jj = 0; jj < 128; jj++) s += qt[(size_t)jj*128] * hp[jj];
            g_qP2[(b*8 + jhalf*4 + quarter)*128 + d] = s;
        } else if (step > 0){
            int lw = (bx - 64)*16 + wid;   // 0..1343
            proj_warps(1344, lw, lane, step-1, pw, pb, out);
        }
        gridbar();

        // ==== P3: energies + softmax partials + ctx partials (0..127) ====
        if (bx < 128){
            int b = bx >> 2, tile = bx & 3, t0 = tile*128;
            for (int i = tid; i < 4096; i += NT){
                int d = i >> 5, k = i & 31;
                sh[d*40 + k]        = g_C1[i];
                sh[5120 + d*40 + k] = g_C2[i];
            }
            if (tid < 128){
                float s = 0.f;
                #pragma unroll
                for (int c = 0; c < 8; c++) s += g_qP2[(b*8 + c)*128 + tid];
                sh[10752 + tid] = s;
                sh[10880 + tid] = __ldg(Ww + tid);
            }
            for (int i = tid; i < 158; i += NT){
                int gi = t0 - 15 + i;
                bool ok = (gi >= 0 && gi < 512);
                sh[11008 + i] = ok ? g_aw [b*512 + gi] : 0.f;
                sh[11168 + i] = ok ? g_aws[b*512 + gi] : 0.f;
            }
            __syncthreads();
            int tt = tid >> 2, sub = tid & 3, t = t0 + tt;
            float ar[32], asr[32];
            #pragma unroll
            for (int k = 0; k < 31; k++){ ar[k] = sh[11008 + tt + k]; asr[k] = sh[11168 + tt + k]; }
            ar[31] = 0.f; asr[31] = 0.f;
            const float* pep = g_peT + (size_t)b*65536 + t;
            float e = 0.f;
            #pragma unroll 1
            for (int dd = 0; dd < 32; dd++){
                int d = dd*4 + sub;
                float l = sh[10752 + d] + __ldg(pep + (size_t)d*512);
                const float4* c14 = (const float4*)(sh + d*40);
                const float4* c24 = (const float4*)(sh + 5120 + d*40);
                #pragma unroll
                for (int i = 0; i < 8; i++){
                    float4 w1 = c14[i], w2 = c24[i];
                    l += ar[i*4]*w1.x + ar[i*4+1]*w1.y + ar[i*4+2]*w1.z + ar[i*4+3]*w1.w;
                    l += asr[i*4]*w2.x + asr[i*4+1]*w2.y + asr[i*4+2]*w2.z + asr[i*4+3]*w2.w;
                }
                e += sh[10880 + d]*tanh_(l);
            }
            e += __shfl_xor_sync(0xffffffffu, e, 1);
            e += __shfl_xor_sync(0xffffffffu, e, 2);
            if (sub == 0){ sh[11328 + tt] = e; g_energy[b*512 + t] = e; }
            __syncthreads();
            if (tid < 128) sh[10240 + tid] = sh[11328 + tid];
            __syncthreads();
            if (tid < 64) sh[10240+tid] = fmaxf(sh[10240+tid], sh[10240+tid+64]);
            __syncthreads();
            if (tid < 32){
                float m = fmaxf(sh[10240+tid], sh[10240+tid+32]);
                #pragma unroll
                for (int o = 16; o; o >>= 1) m = fmaxf(m, __shfl_down_sync(0xffffffffu, m, o));
                if (tid == 0) sh[10240] = m;
            }
            __syncthreads();
            float mi = sh[10240];
            __syncthreads();
            if (tid < 128){
                float p = __expf(sh[11328 + tid] - mi);
                sh[11456 + tid] = p;
                sh[11584 + tid] = p;
            }
            __syncthreads();
            if (tid < 64) sh[11584+tid] += sh[11584+tid+64];
            __syncthreads();
            if (tid < 32){
                float s = sh[11584+tid] + sh[11584+tid+32];
                #pragma unroll
                for (int o = 16; o; o >>= 1) s += __shfl_down_sync(0xffffffffu, s, o);
                if (tid == 0){ g_m[tile*32 + b] = mi; g_s[tile*32 + b] = s; }
            }
            __syncthreads();
            // ctx partial from L2-RESIDENT fp16 enc copy.
            // 512 threads = 2 t-halves x 256 e-pairs; fp32 accumulate; smem combine.
            {
                int th = tid >> 8, p = tid & 255;          // t-half, e-pair
                float2 a2 = make_float2(0.f, 0.f);
                const __half2* ep = g_encH + ((size_t)b*512 + t0 + th*64)*256 + p;
                #pragma unroll 8
                for (int t2 = 0; t2 < 64; t2++){
                    float w = sh[11456 + th*64 + t2];
                    float2 ev = __half22float2(__ldg(&ep[(size_t)t2*256]));
                    a2.x += w*ev.x; a2.y += w*ev.y;
                }
                sh[11712 + th*512 + 2*p]     = a2.x;
                sh[11712 + th*512 + 2*p + 1] = a2.y;
            }
            __syncthreads();
            float acc = sh[11712 + tid] + sh[12224 + tid];
            g_ctxP[((size_t)tile*512 + tid)*32 + b] = acc;
        }
        gridbar();

        // ==== P4: dec GEMM + inline ctx reduce (0..127) | finalize (128..147) ====
        if (bx < 128){
            if (tid < 32){
                int b = tid;
                float m0=g_m[b], m1=g_m[32+b], m2=g_m[64+b], m3=g_m[96+b];
                float M = fmaxf(fmaxf(m0,m1), fmaxf(m2,m3));
                float e0=__expf(m0-M), e1=__expf(m1-M), e2=__expf(m2-M), e3=__expf(m3-M);
                float S = g_s[b]*e0 + g_s[32+b]*e1 + g_s[64+b]*e2 + g_s[96+b]*e3;
                float inv = __fdividef(1.f, S);
                swg[b]=e0*inv; swg[32+b]=e1*inv; swg[64+b]=e2*inv; swg[96+b]=e3*inv;
            }
            __syncthreads();
            const int KSL = 80, KSB = 320;
            int ngrp = bx >> 3, ksM = bx & 7;
            int k0b = ksM*KSB;
            for (int idx = tid; idx < KSB*32; idx += NT){
                int kl = idx >> 5, b = idx & 31, gk = k0b + kl;
                float v;
                if (gk < 1024)      v = g_ahT[gk*32 + b];
                else if (gk < 1536){
                    int o = (gk-1024)*32 + b;
                    v = swg[b]*g_ctxP[o] + swg[32+b]*g_ctxP[16384+o]
                      + swg[64+b]*g_ctxP[32768+o] + swg[96+b]*g_ctxP[49152+o];
                } else               v = g_dhT[(gk-1536)*32 + b];
                *(float2*)(sh + kl*96 + (b>>3)*24 + (b&7)*2) = make_float2(v, v);
            }
            __syncthreads();
            int ntile = ngrp*4 + (wid & 3);
            int ksub = wid >> 2;
            u64 acc[32];
            gemm_core(acc, g_WTd, sh + ksub*KSL*96, k0b + ksub*KSL, ntile, lane, KSL);
            gemm_reduce_write(sh, acc, g_partD2, ngrp, ksM, wid, lane);
        } else {
            for (int b = bx - 128; b < 32; b += 20){
                float m0=g_m[b], m1=g_m[32+b], m2=g_m[64+b], m3=g_m[96+b];
                float M = fmaxf(fmaxf(m0,m1), fmaxf(m2,m3));
                float e0=__expf(m0-M), e1=__expf(m1-M), e2=__expf(m2-M), e3=__expf(m3-M);
                float S = g_s[b]*e0 + g_s[32+b]*e1 + g_s[64+b]*e2 + g_s[96+b]*e3;
                float inv = __fdividef(1.f, S);
                float w0=e0*inv, w1=e1*inv, w2=e2*inv, w3=e3*inv;
                float a = __expf(g_energy[b*512 + tid] - M)*inv;
                g_aw[b*512 + tid] = a;
                g_aws[b*512 + tid] += a;
                __stcs(&out[MEL_TOT + ((size_t)b*512 + step)*512 + tid], a);
                int o = tid*32 + b;
                float v = w0*g_ctxP[o] + w1*g_ctxP[16384+o] + w2*g_ctxP[32768+o] + w3*g_ctxP[49152+o];
                g_ctxT[o] = v;
                g_ctxB[b*512 + tid] = v;
            }
        }
        gridbar();
    }

    // ==== epilogue: dec cell for step 511, then proj(511) ====
    for (int o = gtid; o < 32768; o += GT){
        int b = o >> 10, j = o & 1023;
        float gi = dbih[j]      + dbhh[j]      + part_sum(g_partD2, j, b);
        float gf = dbih[1024+j] + dbhh[1024+j] + part_sum(g_partD2, 1024+j, b);
        float gg = dbih[2048+j] + dbhh[2048+j] + part_sum(g_partD2, 2048+j, b);
        float go = dbih[3072+j] + dbhh[3072+j] + part_sum(g_partD2, 3072+j, b);
        float c  = g_dcT[j*32+b];
        float c2 = sig_(gf)*c + sig_(gi)*tanh_(gg);
        float h  = sig_(go)*tanh_(c2);
        g_dhB[b*1024+j] = h;
    }
    gridbar();
    proj_warps(NB*16, gtid >> 5, lane, 511, pw, pb, out);
}

// ---------------- launch ----------------
extern "C" void kernel_launch(void* const* d_in, const int* in_sizes, int n_in,
                              void* d_out, int out_size){
    const float* enc   = (const float*)d_in[0];
    const float* tgt   = (const float*)d_in[1];
    const float* w1    = (const float*)d_in[2];
    const float* b1    = (const float*)d_in[3];
    const float* w2    = (const float*)d_in[4];
    const float* b2    = (const float*)d_in[5];
    const float* Mw    = (const float*)d_in[6];
    const float* Qw    = (const float*)d_in[7];
    const float* Ww    = (const float*)d_in[8];
    const float* Lw    = (const float*)d_in[9];
    const float* convw = (const float*)d_in[10];
    const float* awih  = (const float*)d_in[11];
    const float* awhh  = (const float*)d_in[12];
    const float* abih  = (const float*)d_in[13];
    const float* abhh  = (const float*)d_in[14];
    const float* dwih  = (const float*)d_in[15];
    const float* dwhh  = (const float*)d_in[16];
    const float* dbih  = (const float*)d_in[17];
    const float* dbhh  = (const float*)d_in[18];
    const float* pw    = (const float*)d_in[19];
    const float* pb    = (const float*)d_in[20];
    float* out = (float*)d_out;

    kprepA<<<22928, 256>>>(tgt, Mw, Lw, convw, awih, awhh, dwih, dwhh, Qw);
    kprepB<<<16384, 256>>>(w1, b1);
    kprepC<<<24576, 256>>>(w2, b2, enc);

    cudaFuncSetAttribute(k_persist, cudaFuncAttributeMaxDynamicSharedMemorySize, 143360);
    k_persist<<<NB, NT, 143360>>>(Ww, abih, abhh, dbih, dbhh, pw, pb, out);
}

// round 16
// speedup vs baseline: 1.1128x; 1.0752x over previous
#include <cuda_runtime.h>
#include <cuda_fp16.h>
#include <math.h>

#define MEL_TOT (32*512*80)
#define NB 148
#define NT 512
#define GT (NB*NT)

typedef unsigned long long u64;

// ---------------- static device scratch ----------------
__device__ __align__(16) float g_tgtT[512*80*32];            // [t][k][b]
__device__ __align__(16) float g_pre1T[(size_t)512*256*32];  // [t][c][b]
__device__ __align__(16) float g_pre2T[(size_t)512*256*32];  // [t][c][b]
__device__ __align__(16) float g_Mt[512*128];                // [k][d]
__device__ __align__(16) float g_peT[(size_t)32*128*512];    // [b][d][t]
__device__ __align__(16) __half2 g_encH[(size_t)32*512*256]; // [b][t][epair] fp16 copy
__device__ __align__(16) float g_C1[128*32], g_C2[128*32];   // [d][k] padded to 32
__device__ __align__(16) float g_WTa[(size_t)1792*4096];     // attn weights k-major [k][n]
__device__ __align__(16) float g_WTd[(size_t)2560*4096];     // dec  weights k-major [k][n]
__device__ __align__(16) float g_QwT[1024*128];              // [j][d]
__device__ __align__(16) float g_partA2[(size_t)8*64*32*64]; // [ks][ntile][b][n]
__device__ __align__(16) float g_partD2[(size_t)8*64*32*64];
__device__ __align__(16) float g_qP2[32*8*128];              // [b][chunk][d]
__device__ __align__(16) float g_ahT[1024*32], g_acT[1024*32]; // [j][b]
__device__ __align__(16) float g_dhT[1024*32], g_dcT[1024*32];
__device__ __align__(16) float g_dhB[32*1024];               // [b][j]
__device__ __align__(16) float g_ctxT[512*32];               // [e][b]
__device__ __align__(16) float g_ctxB[32*512];               // [b][e]
__device__ __align__(16) float g_ctxP[4*512*32];             // [tile][e][b]
__device__ __align__(16) float g_m[4*32], g_s[4*32];         // [tile][b]
__device__ __align__(16) float g_aw[32*512], g_aws[32*512], g_energy[32*512];
__device__ unsigned g_arrive, g_gen;

__device__ __forceinline__ float sig_(float x){
    x = fminf(fmaxf(x, -30.f), 30.f);
    return __fdividef(1.f, 1.f + __expf(-x));
}
__device__ __forceinline__ float tanh_(float x){
    float cx = fminf(fmaxf(x, -15.f), 15.f);
    float e2 = __expf(2.f*cx);
    return __fdividef(e2 - 1.f, e2 + 1.f);
}

// packed fp32x2 FMA (sm_103a FFMA2) — bitwise-identical to 2 scalar fp32 FMAs
__device__ __forceinline__ u64 ffma2(u64 a, u64 b, u64 c){
    u64 d;
    asm("fma.rn.f32x2 %0, %1, %2, %3;" : "=l"(d) : "l"(a), "l"(b), "l"(c));
    return d;
}

// ---------------- prep A: transposes + M^T + C1/C2 + weight k-major + QwT ----------------
__global__ void kprepA(const float* __restrict__ tgt, const float* __restrict__ Mw,
                       const float* __restrict__ Lw, const float* __restrict__ convw,
                       const float* __restrict__ awih, const float* __restrict__ awhh,
                       const float* __restrict__ dwih, const float* __restrict__ dwhh,
                       const float* __restrict__ Qw){
    __shared__ float tile[32][33];
    int bx = blockIdx.x;
    int tx = threadIdx.x & 31, ty = threadIdx.x >> 5;   // 256 threads: 32x8
    if (bx < 5120){
        int idx = bx*256 + threadIdx.x;
        if (idx < 32*512*80){
            int b = idx/(512*80); int r = idx - b*512*80; int t = r/80; int k = r - t*80;
            g_tgtT[((size_t)t*80+k)*32+b] = (t==0) ? 0.f : __ldcs(tgt + idx - 80);
        }
    } else if (bx < 5376){
        int idx = (bx-5120)*256 + threadIdx.x;     // 65536
        int d = idx >> 9, k = idx & 511;
        g_Mt[k*128+d] = Mw[idx];
    } else if (bx < 5392){
        int idx = (bx-5376)*256 + threadIdx.x;     // 4096
        int d = idx >> 5, k = idx & 31;
        float c1 = 0.f, c2 = 0.f;
        if (k < 31){
            for (int f = 0; f < 32; f++){
                float lw = Lw[d*32+f];
                c1 += lw*convw[f*62+k];
                c2 += lw*convw[f*62+31+k];
            }
        }
        g_C1[idx] = c1; g_C2[idx] = c2;
    } else if (bx < 12560){
        int b2 = bx - 5392;                        // attn: 56 k-tiles x 128 n-tiles
        int kt = b2 % 56, ntb = b2 / 56;
        int k0 = kt*32, n0 = ntb*32;
        #pragma unroll
        for (int i = 0; i < 32; i += 8){
            int n = n0 + ty + i, k = k0 + tx;
            float v = (k < 768) ? awih[(size_t)n*768 + k] : awhh[(size_t)n*1024 + k - 768];
            tile[ty+i][tx] = v;
        }
        __syncthreads();
        #pragma unroll
        for (int i = 0; i < 32; i += 8)
            g_WTa[(size_t)(k0 + ty + i)*4096 + n0 + tx] = tile[tx][ty+i];
    } else if (bx < 22800){
        int b2 = bx - 12560;                       // dec: 80 k-tiles x 128 n-tiles
        int kt = b2 % 80, ntb = b2 / 80;
        int k0 = kt*32, n0 = ntb*32;
        #pragma unroll
        for (int i = 0; i < 32; i += 8){
            int n = n0 + ty + i, k = k0 + tx;
            float v = (k < 1536) ? dwih[(size_t)n*1536 + k] : dwhh[(size_t)n*1024 + k - 1536];
            tile[ty+i][tx] = v;
        }
        __syncthreads();
        #pragma unroll
        for (int i = 0; i < 32; i += 8)
            g_WTd[(size_t)(k0 + ty + i)*4096 + n0 + tx] = tile[tx][ty+i];
    } else {
        int b2 = bx - 22800;                       // 128: Qw[128][1024] -> QwT[1024][128]
        int jt = b2 >> 2, dt = b2 & 3;
        int j0 = jt*32, d0 = dt*32;
        #pragma unroll
        for (int i = 0; i < 32; i += 8)
            tile[ty+i][tx] = Qw[(size_t)(d0 + ty + i)*1024 + j0 + tx];
        __syncthreads();
        #pragma unroll
        for (int i = 0; i < 32; i += 8)
            g_QwT[(size_t)(j0 + ty + i)*128 + d0 + tx] = tile[tx][ty+i];
    }
}

// ---------------- prep B: prenet layer 1 ----------------
__global__ void kprepB(const float* __restrict__ w1, const float* __restrict__ b1){
    int gw = blockIdx.x*8 + (threadIdx.x >> 5);
    int lane = threadIdx.x & 31;
    int t = gw >> 8, c = gw & 255;
    float acc = b1[c];
    const float4* w4 = (const float4*)(w1 + c*80);
    #pragma unroll
    for (int k = 0; k < 80; k += 4){
        float4 wv = __ldg(&w4[k >> 2]);
        const float* xp = g_tgtT + ((size_t)t*80 + k)*32 + lane;
        acc += wv.x*xp[0] + wv.y*xp[32] + wv.z*xp[64] + wv.w*xp[96];
    }
    g_pre1T[((size_t)t*256 + c)*32 + lane] = fmaxf(acc, 0.f);
}

// ---------------- prep C: prenet layer 2 + processed_enc + fp16 enc copy ----------------
__global__ void kprepC(const float* __restrict__ w2, const float* __restrict__ b2,
                       const float* __restrict__ enc){
    if (blockIdx.x < 16384){
        int gw = blockIdx.x*8 + (threadIdx.x >> 5);
        int lane = threadIdx.x & 31;
        int t = gw >> 8, c = gw & 255;
        float acc = b2[c];
        const float4* w4 = (const float4*)(w2 + c*256);
        #pragma unroll 4
        for (int k = 0; k < 256; k += 4){
            float4 wv = __ldg(&w4[k >> 2]);
            const float* xp = g_pre1T + ((size_t)t*256 + k)*32 + lane;
            acc += wv.x*xp[0] + wv.y*xp[32] + wv.z*xp[64] + wv.w*xp[96];
        }
        g_pre2T[((size_t)t*256 + c)*32 + lane] = fmaxf(acc, 0.f);
    } else {
        __shared__ float es[1024];
        int pb2 = blockIdx.x - 16384;               // 8192 blocks, 2 bt each
        int half = threadIdx.x >> 7, tid2 = threadIdx.x & 127;
        int bt = pb2*2 + half;
        float* esh = es + half*512;
        const float* ep = enc + (size_t)bt*512;
        for (int i = tid2; i < 512; i += 128) esh[i] = __ldcs(ep + i);
        __syncthreads();
        // fp16 copy of this enc row (256 half2 per bt)
        for (int i = tid2; i < 256; i += 128)
            g_encH[(size_t)bt*256 + i] = __floats2half2_rn(esh[2*i], esh[2*i+1]);
        float acc = 0.f;
        #pragma unroll 4
        for (int k = 0; k < 512; k += 4){
            const float* mp = g_Mt + (size_t)k*128 + tid2;
            acc += esh[k]*mp[0] + esh[k+1]*mp[128] + esh[k+2]*mp[256] + esh[k+3]*mp[384];
        }
        int b = bt >> 9, t = bt & 511;
        g_peT[(size_t)b*65536 + tid2*512 + t] = acc;   // [b][d][t]
    }
}

// ---------------- grid barrier ----------------
__device__ __forceinline__ void gridbar(){
    __syncthreads();
    if (threadIdx.x == 0){
        unsigned gen = *((volatile unsigned*)&g_gen);
        __threadfence();
        unsigned prev = atomicAdd(&g_arrive, 1u);
        if (prev == NB - 1){
            g_arrive = 0;
            __threadfence();
            atomicAdd(&g_gen, 1u);
        } else {
            while (*((volatile unsigned*)&g_gen) == gen) __nanosleep(32);
        }
        __threadfence();
    }
    __syncthreads();
}

// ---------------- register-tiled GEMV core with weight prefetch ----------------
__device__ __forceinline__ void gemm_core(u64 acc[32], const float* __restrict__ WT,
        const float* __restrict__ xs, int k0, int ntile, int lane, int KSL)
{
    int ng = lane >> 2, bg = lane & 3;
    const float* wb = WT + (size_t)k0*4096 + ntile*64 + ng*8;
    const float* xb = xs + bg*24;
    #pragma unroll
    for (int i = 0; i < 32; i++) acc[i] = 0ull;
    ulonglong2 wA = *(const ulonglong2*)(wb);
    ulonglong2 wB = *(const ulonglong2*)(wb + 4);
    #pragma unroll 2
    for (int kl = 0; kl < KSL; kl++){
        int kn = (kl + 1 < KSL) ? kl + 1 : kl;
        ulonglong2 wA2 = *(const ulonglong2*)(wb + (size_t)kn*4096);
        ulonglong2 wB2 = *(const ulonglong2*)(wb + (size_t)kn*4096 + 4);
        const float* xr = xb + kl*96;
        ulonglong2 xA = *(const ulonglong2*)(xr);
        ulonglong2 xB = *(const ulonglong2*)(xr + 4);
        ulonglong2 xC = *(const ulonglong2*)(xr + 8);
        ulonglong2 xD = *(const ulonglong2*)(xr + 12);
        u64 xv[8] = {xA.x, xA.y, xB.x, xB.y, xC.x, xC.y, xD.x, xD.y};
        #pragma unroll
        for (int j = 0; j < 8; j++){
            acc[j]      = ffma2(wA.x, xv[j], acc[j]);
            acc[8 + j]  = ffma2(wA.y, xv[j], acc[8 + j]);
            acc[16 + j] = ffma2(wB.x, xv[j], acc[16 + j]);
            acc[24 + j] = ffma2(wB.y, xv[j], acc[24 + j]);
        }
        wA = wA2; wB = wB2;
    }
}

// in-block 4-way k-reduce via smem, coalesced global write of 8-ks partials
__device__ __forceinline__ void gemm_reduce_write(float* __restrict__ sh, u64 acc[32],
        float* __restrict__ gpart, int ngrp, int ksM, int wid, int lane)
{
    __syncthreads();                       // xs fully consumed
    {
        float* rp = sh + wid*2176 + lane*68;
        #pragma unroll
        for (int j = 0; j < 8; j++){
            #pragma unroll
            for (int np = 0; np < 4; np++)
                *(u64*)(rp + j*8 + np*2) = acc[np*8 + j];
        }
    }
    __syncthreads();
    if (wid < 4){
        int nt = ngrp*4 + wid;
        float* outp = gpart + (((size_t)ksM*64 + nt)*32)*64;
        int ngr = lane >> 2, npr = lane & 3;
        for (int b = 0; b < 32; b++){
            int bg = b >> 3, j = b & 7;
            float2 s = make_float2(0.f, 0.f);
            #pragma unroll
            for (int r = 0; r < 4; r++){
                float2 v = *(float2*)(sh + (wid + r*4)*2176 + (ngr*4 + bg)*68 + j*8 + npr*2);
                s.x += v.x; s.y += v.y;
            }
            *(float2*)(outp + b*64 + lane*2) = s;
        }
    }
}

// sum the 8 k-split partials for output row n, batch b
__device__ __forceinline__ float part_sum(const float* __restrict__ gpart, int n, int b){
    int ntile = n >> 6, nin = n & 63;
    const float* p = gpart + ((size_t)ntile*32 + b)*64 + nin;
    float s = 0.f;
    #pragma unroll
    for (int ks = 0; ks < 8; ks++) s += p[(size_t)ks*131072];
    return s;
}

// ---------------- output projection (coalesced via dhB/ctxB) ----------------
__device__ __forceinline__ void proj_warps(int nwarp, int lw, int lane, int step,
        const float* __restrict__ pw, const float* __restrict__ pb, float* __restrict__ out){
    for (int o = lw; o < 2560; o += nwarp){
        int mrow = o >> 5, b = o & 31;
        float s = 0.f;
        const float4* w4 = (const float4*)(pw + (size_t)mrow*1536);
        const float4* h4 = (const float4*)(g_dhB + b*1024);
        #pragma unroll
        for (int it = 0; it < 8; it++){
            int j4 = it*32 + lane;
            float4 w = __ldg(&w4[j4]);
            float4 h = h4[j4];
            s += w.x*h.x + w.y*h.y + w.z*h.z + w.w*h.w;
        }
        const float4* c4 = (const float4*)(g_ctxB + b*512);
        #pragma unroll
        for (int it = 0; it < 4; it++){
            int j4 = it*32 + lane;
            float4 w = __ldg(&w4[256 + j4]);
            float4 c = c4[j4];
            s += w.x*c.x + w.y*c.y + w.z*c.z + w.w*c.w;
        }
        #pragma unroll
        for (int off = 16; off; off >>= 1) s += __shfl_down_sync(0xffffffffu, s, off);
        if (lane == 0) __stcs(&out[((size_t)b*512 + step)*80 + mrow], s + __ldg(pb + mrow));
    }
}

// ---------------- persistent decoder ----------------
__global__ void __launch_bounds__(NT, 1) k_persist(
    const float* __restrict__ Ww,
    const float* __restrict__ abih, const float* __restrict__ abhh,
    const float* __restrict__ dbih, const float* __restrict__ dbhh,
    const float* __restrict__ pw,   const float* __restrict__ pb,
    float* __restrict__ out)
{
    extern __shared__ float sh[];
    __shared__ float swg[128];
    const int tid  = threadIdx.x;
    const int bx   = blockIdx.x;
    const int gtid = bx*NT + tid;
    const int lane = tid & 31;
    const int wid  = tid >> 5;

    for (int i = gtid; i < 32768; i += GT){ g_ahT[i]=0.f; g_acT[i]=0.f; g_dhT[i]=0.f; g_dcT[i]=0.f; g_dhB[i]=0.f; }
    for (int i = gtid; i < 16384; i += GT){ g_ctxT[i]=0.f; g_ctxB[i]=0.f; g_aw[i]=0.f; g_aws[i]=0.f; }
    gridbar();

    for (int step = 0; step < 512; step++){
        // ==== P1: attn GEMM (0..127) | dec cell(step-1) (128..147) ====
        if (bx < 128){
            const int KSL = 56, KSB = 224;
            int ngrp = bx >> 3, ksM = bx & 7;
            int k0b = ksM*KSB;
            for (int idx = tid; idx < KSB*32; idx += NT){
                int kl = idx >> 5, b = idx & 31, gk = k0b + kl;
                float v;
                if (gk < 256)      v = __ldcs(&g_pre2T[((size_t)step*256 + gk)*32 + b]);
                else if (gk < 768) v = g_ctxT[(gk-256)*32 + b];
                else               v = g_ahT[(gk-768)*32 + b];
                *(float2*)(sh + kl*96 + (b>>3)*24 + (b&7)*2) = make_float2(v, v);
            }
            __syncthreads();
            int ntile = ngrp*4 + (wid & 3);
            int ksub = wid >> 2;
            u64 acc[32];
            gemm_core(acc, g_WTa, sh + ksub*KSL*96, k0b + ksub*KSL, ntile, lane, KSL);
            gemm_reduce_write(sh, acc, g_partA2, ngrp, ksM, wid, lane);
        } else if (step > 0){
            for (int o = (bx-128)*NT + tid; o < 32768; o += 20*NT){
                int b = o >> 10, j = o & 1023;
                float gi = dbih[j]      + dbhh[j]      + part_sum(g_partD2, j, b);
                float gf = dbih[1024+j] + dbhh[1024+j] + part_sum(g_partD2, 1024+j, b);
                float gg = dbih[2048+j] + dbhh[2048+j] + part_sum(g_partD2, 2048+j, b);
                float go = dbih[3072+j] + dbhh[3072+j] + part_sum(g_partD2, 3072+j, b);
                float c  = g_dcT[j*32+b];
                float c2 = sig_(gf)*c + sig_(gi)*tanh_(gg);
                float h  = sig_(go)*tanh_(c2);
                g_dcT[j*32+b] = c2;
                g_dhT[j*32+b] = h;
                g_dhB[b*1024+j] = h;
            }
        }
        gridbar();

        // ==== P2: attn cell + q partials (0..63) | proj(step-1) (64..147) ====
        if (bx < 64){
            int b = bx >> 1, jhalf = bx & 1;
            int j = (jhalf << 9) + tid;
            float gi = abih[j]      + abhh[j]      + part_sum(g_partA2, j, b);
            float gf = abih[1024+j] + abhh[1024+j] + part_sum(g_partA2, 1024+j, b);
            float gg = abih[2048+j] + abhh[2048+j] + part_sum(g_partA2, 2048+j, b);
            float go = abih[3072+j] + abhh[3072+j] + part_sum(g_partA2, 3072+j, b);
            float c  = g_acT[j*32+b];
            float c2 = sig_(gf)*c + sig_(gi)*tanh_(gg);
            float h  = sig_(go)*tanh_(c2);
            g_acT[j*32+b] = c2;
            g_ahT[j*32+b] = h;
            sh[tid] = h;
            __syncthreads();
            int d = tid & 127, quarter = tid >> 7;
            const float* qt = g_QwT + ((size_t)(jhalf*512 + quarter*128))*128 + d;
            const float* hp = sh + quarter*128;
            float s = 0.f;
            #pragma unroll 8
            for (int jj = 0; jj < 128; jj++) s += qt[(size_t)jj*128] * hp[jj];
            g_qP2[(b*8 + jhalf*4 + quarter)*128 + d] = s;
        } else if (step > 0){
            int lw = (bx - 64)*16 + wid;   // 0..1343
            proj_warps(1344, lw, lane, step-1, pw, pb, out);
        }
        gridbar();

        // ==== P3: energies + softmax partials + ctx partials (0..127) ====
        if (bx < 128){
            int b = bx >> 2, tile = bx & 3, t0 = tile*128;
            for (int i = tid; i < 4096; i += NT){
                int d = i >> 5, k = i & 31;
                sh[d*40 + k]        = g_C1[i];
                sh[5120 + d*40 + k] = g_C2[i];
            }
            if (tid < 128){
                float s = 0.f;
                #pragma unroll
                for (int c = 0; c < 8; c++) s += g_qP2[(b*8 + c)*128 + tid];
                sh[10752 + tid] = s;
                sh[10880 + tid] = __ldg(Ww + tid);
            }
            for (int i = tid; i < 158; i += NT){
                int gi = t0 - 15 + i;
                bool ok = (gi >= 0 && gi < 512);
                sh[11008 + i] = ok ? g_aw [b*512 + gi] : 0.f;
                sh[11168 + i] = ok ? g_aws[b*512 + gi] : 0.f;
            }
            __syncthreads();
            int tt = tid >> 2, sub = tid & 3, t = t0 + tt;
            float ar[32], asr[32];
            #pragma unroll
            for (int k = 0; k < 31; k++){ ar[k] = sh[11008 + tt + k]; asr[k] = sh[11168 + tt + k]; }
            ar[31] = 0.f; asr[31] = 0.f;
            const float* pep = g_peT + (size_t)b*65536 + t;
            float e = 0.f;
            #pragma unroll 1
            for (int dd = 0; dd < 32; dd++){
                int d = dd*4 + sub;
                float l = sh[10752 + d] + __ldg(pep + (size_t)d*512);
                const float4* c14 = (const float4*)(sh + d*40);
                const float4* c24 = (const float4*)(sh + 5120 + d*40);
                #pragma unroll
                for (int i = 0; i < 8; i++){
                    float4 w1 = c14[i], w2 = c24[i];
                    l += ar[i*4]*w1.x + ar[i*4+1]*w1.y + ar[i*4+2]*w1.z + ar[i*4+3]*w1.w;
                    l += asr[i*4]*w2.x + asr[i*4+1]*w2.y + asr[i*4+2]*w2.z + asr[i*4+3]*w2.w;
                }
                e += sh[10880 + d]*tanh_(l);
            }
            e += __shfl_xor_sync(0xffffffffu, e, 1);
            e += __shfl_xor_sync(0xffffffffu, e, 2);
            if (sub == 0){ sh[11328 + tt] = e; g_energy[b*512 + t] = e; }
            __syncthreads();
            if (tid < 128) sh[10240 + tid] = sh[11328 + tid];
            __syncthreads();
            if (tid < 64) sh[10240+tid] = fmaxf(sh[10240+tid], sh[10240+tid+64]);
            __syncthreads();
            if (tid < 32){
                float m = fmaxf(sh[10240+tid], sh[10240+tid+32]);
                #pragma unroll
                for (int o = 16; o; o >>= 1) m = fmaxf(m, __shfl_down_sync(0xffffffffu, m, o));
                if (tid == 0) sh[10240] = m;
            }
            __syncthreads();
            float mi = sh[10240];
            __syncthreads();
            if (tid < 128){
                float p = __expf(sh[11328 + tid] - mi);
                sh[11456 + tid] = p;
                sh[11584 + tid] = p;
            }
            __syncthreads();
            if (tid < 64) sh[11584+tid] += sh[11584+tid+64];
            __syncthreads();
            if (tid < 32){
                float s = sh[11584+tid] + sh[11584+tid+32];
                #pragma unroll
                for (int o = 16; o; o >>= 1) s += __shfl_down_sync(0xffffffffu, s, o);
                if (tid == 0){ g_m[tile*32 + b] = mi; g_s[tile*32 + b] = s; }
            }
            __syncthreads();
            // ctx partial from STREAMED fp16 enc copy (evict-first: keeps the
            // weight hot-set resident; 16 MB/step DRAM vs 32 MB for fp32 enc).
            {
                int th = tid >> 8, p = tid & 255;          // t-half, e-pair
                float2 a2 = make_float2(0.f, 0.f);
                const __half2* ep = g_encH + ((size_t)b*512 + t0 + th*64)*256 + p;
                #pragma unroll 8
                for (int t2 = 0; t2 < 64; t2++){
                    float w = sh[11456 + th*64 + t2];
                    float2 ev = __half22float2(__ldcs(&ep[(size_t)t2*256]));
                    a2.x += w*ev.x; a2.y += w*ev.y;
                }
                sh[11712 + th*512 + 2*p]     = a2.x;
                sh[11712 + th*512 + 2*p + 1] = a2.y;
            }
            __syncthreads();
            float acc = sh[11712 + tid] + sh[12224 + tid];
            g_ctxP[((size_t)tile*512 + tid)*32 + b] = acc;
        }
        gridbar();

        // ==== P4: dec GEMM + inline ctx reduce (0..127) | finalize (128..147) ====
        if (bx < 128){
            if (tid < 32){
                int b = tid;
                float m0=g_m[b], m1=g_m[32+b], m2=g_m[64+b], m3=g_m[96+b];
                float M = fmaxf(fmaxf(m0,m1), fmaxf(m2,m3));
                float e0=__expf(m0-M), e1=__expf(m1-M), e2=__expf(m2-M), e3=__expf(m3-M);
                float S = g_s[b]*e0 + g_s[32+b]*e1 + g_s[64+b]*e2 + g_s[96+b]*e3;
                float inv = __fdividef(1.f, S);
                swg[b]=e0*inv; swg[32+b]=e1*inv; swg[64+b]=e2*inv; swg[96+b]=e3*inv;
            }
            __syncthreads();
            const int KSL = 80, KSB = 320;
            int ngrp = bx >> 3, ksM = bx & 7;
            int k0b = ksM*KSB;
            for (int idx = tid; idx < KSB*32; idx += NT){
                int kl = idx >> 5, b = idx & 31, gk = k0b + kl;
                float v;
                if (gk < 1024)      v = g_ahT[gk*32 + b];
                else if (gk < 1536){
                    int o = (gk-1024)*32 + b;
                    v = swg[b]*g_ctxP[o] + swg[32+b]*g_ctxP[16384+o]
                      + swg[64+b]*g_ctxP[32768+o] + swg[96+b]*g_ctxP[49152+o];
                } else               v = g_dhT[(gk-1536)*32 + b];
                *(float2*)(sh + kl*96 + (b>>3)*24 + (b&7)*2) = make_float2(v, v);
            }
            __syncthreads();
            int ntile = ngrp*4 + (wid & 3);
            int ksub = wid >> 2;
            u64 acc[32];
            gemm_core(acc, g_WTd, sh + ksub*KSL*96, k0b + ksub*KSL, ntile, lane, KSL);
            gemm_reduce_write(sh, acc, g_partD2, ngrp, ksM, wid, lane);
        } else {
            for (int b = bx - 128; b < 32; b += 20){
                float m0=g_m[b], m1=g_m[32+b], m2=g_m[64+b], m3=g_m[96+b];
                float M = fmaxf(fmaxf(m0,m1), fmaxf(m2,m3));
                float e0=__expf(m0-M), e1=__expf(m1-M), e2=__expf(m2-M), e3=__expf(m3-M);
                float S = g_s[b]*e0 + g_s[32+b]*e1 + g_s[64+b]*e2 + g_s[96+b]*e3;
                float inv = __fdividef(1.f, S);
                float w0=e0*inv, w1=e1*inv, w2=e2*inv, w3=e3*inv;
                float a = __expf(g_energy[b*512 + tid] - M)*inv;
                g_aw[b*512 + tid] = a;
                g_aws[b*512 + tid] += a;
                __stcs(&out[MEL_TOT + ((size_t)b*512 + step)*512 + tid], a);
                int o = tid*32 + b;
                float v = w0*g_ctxP[o] + w1*g_ctxP[16384+o] + w2*g_ctxP[32768+o] + w3*g_ctxP[49152+o];
                g_ctxT[o] = v;
                g_ctxB[b*512 + tid] = v;
            }
        }
        gridbar();
    }

    // ==== epilogue: dec cell for step 511, then proj(511) ====
    for (int o = gtid; o < 32768; o += GT){
        int b = o >> 10, j = o & 1023;
        float gi = dbih[j]      + dbhh[j]      + part_sum(g_partD2, j, b);
        float gf = dbih[1024+j] + dbhh[1024+j] + part_sum(g_partD2, 1024+j, b);
        float gg = dbih[2048+j] + dbhh[2048+j] + part_sum(g_partD2, 2048+j, b);
        float go = dbih[3072+j] + dbhh[3072+j] + part_sum(g_partD2, 3072+j, b);
        float c  = g_dcT[j*32+b];
        float c2 = sig_(gf)*c + sig_(gi)*tanh_(gg);
        float h  = sig_(go)*tanh_(c2);
        g_dhB[b*1024+j] = h;
    }
    gridbar();
    proj_warps(NB*16, gtid >> 5, lane, 511, pw, pb, out);
}

// ---------------- launch ----------------
extern "C" void kernel_launch(void* const* d_in, const int* in_sizes, int n_in,
                              void* d_out, int out_size){
    const float* enc   = (const float*)d_in[0];
    const float* tgt   = (const float*)d_in[1];
    const float* w1    = (const float*)d_in[2];
    const float* b1    = (const float*)d_in[3];
    const float* w2    = (const float*)d_in[4];
    const float* b2    = (const float*)d_in[5];
    const float* Mw    = (const float*)d_in[6];
    const float* Qw    = (const float*)d_in[7];
    const float* Ww    = (const float*)d_in[8];
    const float* Lw    = (const float*)d_in[9];
    const float* convw = (const float*)d_in[10];
    const float* awih  = (const float*)d_in[11];
    const float* awhh  = (const float*)d_in[12];
    const float* abih  = (const float*)d_in[13];
    const float* abhh  = (const float*)d_in[14];
    const float* dwih  = (const float*)d_in[15];
    const float* dwhh  = (const float*)d_in[16];
    const float* dbih  = (const float*)d_in[17];
    const float* dbhh  = (const float*)d_in[18];
    const float* pw    = (const float*)d_in[19];
    const float* pb    = (const float*)d_in[20];
    float* out = (float*)d_out;

    kprepA<<<22928, 256>>>(tgt, Mw, Lw, convw, awih, awhh, dwih, dwhh, Qw);
    kprepB<<<16384, 256>>>(w1, b1);
    kprepC<<<24576, 256>>>(w2, b2, enc);

    cudaFuncSetAttribute(k_persist, cudaFuncAttributeMaxDynamicSharedMemorySize, 143360);
    k_persist<<<NB, NT, 143360>>>(Ww, abih, abhh, dbih, dbhh, pw, pb, out);
}

// round 17
// speedup vs baseline: 1.2027x; 1.0808x over previous
#include <cuda_runtime.h>
#include <cuda_fp16.h>
#include <math.h>

#define MEL_TOT (32*512*80)
#define NB 148
#define NT 512
#define GT (NB*NT)

typedef unsigned long long u64;

// ---------------- static device scratch ----------------
__device__ __align__(16) float g_tgtT[512*80*32];            // [t][k][b]
__device__ __align__(16) float g_pre1T[(size_t)512*256*32];  // [t][c][b]
__device__ __align__(16) float g_pre2T[(size_t)512*256*32];  // [t][c][b]
__device__ __align__(16) float g_Mt[512*128];                // [k][d]
__device__ __align__(16) float g_peT[(size_t)32*128*512];    // [b][d][t]
__device__ __align__(16) __half2 g_encH[(size_t)32*512*256]; // [b][t][epair] fp16 copy
__device__ __align__(16) float g_C1[128*32], g_C2[128*32];   // [d][k] padded to 32
__device__ __align__(16) __half g_WTa[(size_t)1792*4096];    // attn weights k-major fp16
__device__ __align__(16) __half g_WTd[(size_t)2560*4096];    // dec  weights k-major fp16
__device__ __align__(16) float g_QwT[1024*128];              // [j][d]
__device__ __align__(16) float g_partA2[(size_t)8*64*32*64]; // [ks][ntile][b][n]
__device__ __align__(16) float g_partD2[(size_t)8*64*32*64];
__device__ __align__(16) float g_qP2[32*8*128];              // [b][chunk][d]
__device__ __align__(16) float g_ahT[1024*32], g_acT[1024*32]; // [j][b]
__device__ __align__(16) float g_dhT[1024*32], g_dcT[1024*32];
__device__ __align__(16) float g_dhB[32*1024];               // [b][j]
__device__ __align__(16) float g_ctxT[512*32];               // [e][b]
__device__ __align__(16) float g_ctxB[32*512];               // [b][e]
__device__ __align__(16) float g_ctxP[4*512*32];             // [tile][e][b]
__device__ __align__(16) float g_m[4*32], g_s[4*32];         // [tile][b]
__device__ __align__(16) float g_aw[32*512], g_aws[32*512], g_energy[32*512];
__device__ unsigned g_arrive, g_gen;

__device__ __forceinline__ float sig_(float x){
    x = fminf(fmaxf(x, -30.f), 30.f);
    return __fdividef(1.f, 1.f + __expf(-x));
}
__device__ __forceinline__ float tanh_(float x){
    float cx = fminf(fmaxf(x, -15.f), 15.f);
    float e2 = __expf(2.f*cx);
    return __fdividef(e2 - 1.f, e2 + 1.f);
}

// packed fp32x2 FMA (sm_103a FFMA2)
__device__ __forceinline__ u64 ffma2(u64 a, u64 b, u64 c){
    u64 d;
    asm("fma.rn.f32x2 %0, %1, %2, %3;" : "=l"(d) : "l"(a), "l"(b), "l"(c));
    return d;
}
__device__ __forceinline__ u64 h2u(__half2 h){
    float2 f = __half22float2(h);
    return *(u64*)&f;
}

// ---------------- prep A: transposes + M^T + C1/C2 + fp16 weight k-major + QwT --------
__global__ void kprepA(const float* __restrict__ tgt, const float* __restrict__ Mw,
                       const float* __restrict__ Lw, const float* __restrict__ convw,
                       const float* __restrict__ awih, const float* __restrict__ awhh,
                       const float* __restrict__ dwih, const float* __restrict__ dwhh,
                       const float* __restrict__ Qw){
    __shared__ float tile[32][33];
    int bx = blockIdx.x;
    int tx = threadIdx.x & 31, ty = threadIdx.x >> 5;   // 256 threads: 32x8
    if (bx < 5120){
        int idx = bx*256 + threadIdx.x;
        if (idx < 32*512*80){
            int b = idx/(512*80); int r = idx - b*512*80; int t = r/80; int k = r - t*80;
            g_tgtT[((size_t)t*80+k)*32+b] = (t==0) ? 0.f : __ldcs(tgt + idx - 80);
        }
    } else if (bx < 5376){
        int idx = (bx-5120)*256 + threadIdx.x;     // 65536
        int d = idx >> 9, k = idx & 511;
        g_Mt[k*128+d] = Mw[idx];
    } else if (bx < 5392){
        int idx = (bx-5376)*256 + threadIdx.x;     // 4096
        int d = idx >> 5, k = idx & 31;
        float c1 = 0.f, c2 = 0.f;
        if (k < 31){
            for (int f = 0; f < 32; f++){
                float lw = Lw[d*32+f];
                c1 += lw*convw[f*62+k];
                c2 += lw*convw[f*62+31+k];
            }
        }
        g_C1[idx] = c1; g_C2[idx] = c2;
    } else if (bx < 12560){
        int b2 = bx - 5392;                        // attn: 56 k-tiles x 128 n-tiles
        int kt = b2 % 56, ntb = b2 / 56;
        int k0 = kt*32, n0 = ntb*32;
        #pragma unroll
        for (int i = 0; i < 32; i += 8){
            int n = n0 + ty + i, k = k0 + tx;
            float v = (k < 768) ? awih[(size_t)n*768 + k] : awhh[(size_t)n*1024 + k - 768];
            tile[ty+i][tx] = v;
        }
        __syncthreads();
        #pragma unroll
        for (int i = 0; i < 32; i += 8)
            g_WTa[(size_t)(k0 + ty + i)*4096 + n0 + tx] = __float2half_rn(tile[tx][ty+i]);
    } else if (bx < 22800){
        int b2 = bx - 12560;                       // dec: 80 k-tiles x 128 n-tiles
        int kt = b2 % 80, ntb = b2 / 80;
        int k0 = kt*32, n0 = ntb*32;
        #pragma unroll
        for (int i = 0; i < 32; i += 8){
            int n = n0 + ty + i, k = k0 + tx;
            float v = (k < 1536) ? dwih[(size_t)n*1536 + k] : dwhh[(size_t)n*1024 + k - 1536];
            tile[ty+i][tx] = v;
        }
        __syncthreads();
        #pragma unroll
        for (int i = 0; i < 32; i += 8)
            g_WTd[(size_t)(k0 + ty + i)*4096 + n0 + tx] = __float2half_rn(tile[tx][ty+i]);
    } else {
        int b2 = bx - 22800;                       // 128: Qw[128][1024] -> QwT[1024][128]
        int jt = b2 >> 2, dt = b2 & 3;
        int j0 = jt*32, d0 = dt*32;
        #pragma unroll
        for (int i = 0; i < 32; i += 8)
            tile[ty+i][tx] = Qw[(size_t)(d0 + ty + i)*1024 + j0 + tx];
        __syncthreads();
        #pragma unroll
        for (int i = 0; i < 32; i += 8)
            g_QwT[(size_t)(j0 + ty + i)*128 + d0 + tx] = tile[tx][ty+i];
    }
}

// ---------------- prep B: prenet layer 1 ----------------
__global__ void kprepB(const float* __restrict__ w1, const float* __restrict__ b1){
    int gw = blockIdx.x*8 + (threadIdx.x >> 5);
    int lane = threadIdx.x & 31;
    int t = gw >> 8, c = gw & 255;
    float acc = b1[c];
    const float4* w4 = (const float4*)(w1 + c*80);
    #pragma unroll
    for (int k = 0; k < 80; k += 4){
        float4 wv = __ldg(&w4[k >> 2]);
        const float* xp = g_tgtT + ((size_t)t*80 + k)*32 + lane;
        acc += wv.x*xp[0] + wv.y*xp[32] + wv.z*xp[64] + wv.w*xp[96];
    }
    g_pre1T[((size_t)t*256 + c)*32 + lane] = fmaxf(acc, 0.f);
}

// ---------------- prep C: prenet layer 2 + processed_enc + fp16 enc copy ----------------
__global__ void kprepC(const float* __restrict__ w2, const float* __restrict__ b2,
                       const float* __restrict__ enc){
    if (blockIdx.x < 16384){
        int gw = blockIdx.x*8 + (threadIdx.x >> 5);
        int lane = threadIdx.x & 31;
        int t = gw >> 8, c = gw & 255;
        float acc = b2[c];
        const float4* w4 = (const float4*)(w2 + c*256);
        #pragma unroll 4
        for (int k = 0; k < 256; k += 4){
            float4 wv = __ldg(&w4[k >> 2]);
            const float* xp = g_pre1T + ((size_t)t*256 + k)*32 + lane;
            acc += wv.x*xp[0] + wv.y*xp[32] + wv.z*xp[64] + wv.w*xp[96];
        }
        g_pre2T[((size_t)t*256 + c)*32 + lane] = fmaxf(acc, 0.f);
    } else {
        __shared__ float es[1024];
        int pb2 = blockIdx.x - 16384;               // 8192 blocks, 2 bt each
        int half = threadIdx.x >> 7, tid2 = threadIdx.x & 127;
        int bt = pb2*2 + half;
        float* esh = es + half*512;
        const float* ep = enc + (size_t)bt*512;
        for (int i = tid2; i < 512; i += 128) esh[i] = __ldcs(ep + i);
        __syncthreads();
        for (int i = tid2; i < 256; i += 128)
            g_encH[(size_t)bt*256 + i] = __floats2half2_rn(esh[2*i], esh[2*i+1]);
        float acc = 0.f;
        #pragma unroll 4
        for (int k = 0; k < 512; k += 4){
            const float* mp = g_Mt + (size_t)k*128 + tid2;
            acc += esh[k]*mp[0] + esh[k+1]*mp[128] + esh[k+2]*mp[256] + esh[k+3]*mp[384];
        }
        int b = bt >> 9, t = bt & 511;
        g_peT[(size_t)b*65536 + tid2*512 + t] = acc;   // [b][d][t]
    }
}

// ---------------- grid barrier ----------------
__device__ __forceinline__ void gridbar(){
    __syncthreads();
    if (threadIdx.x == 0){
        unsigned gen = *((volatile unsigned*)&g_gen);
        __threadfence();
        unsigned prev = atomicAdd(&g_arrive, 1u);
        if (prev == NB - 1){
            g_arrive = 0;
            __threadfence();
            atomicAdd(&g_gen, 1u);
        } else {
            while (*((volatile unsigned*)&g_gen) == gen) __nanosleep(32);
        }
        __threadfence();
    }
    __syncthreads();
}

// ---------------- register-tiled GEMV core, fp16 weights + fp32 accumulate ----------
__device__ __forceinline__ void gemm_core(u64 acc[32], const __half* __restrict__ WT,
        const float* __restrict__ xs, int k0, int ntile, int lane, int KSL)
{
    int ng = lane >> 2, bg = lane & 3;
    const __half* wb = WT + (size_t)k0*4096 + ntile*64 + ng*8;
    const float* xb = xs + bg*24;
    #pragma unroll
    for (int i = 0; i < 32; i++) acc[i] = 0ull;
    ulonglong2 wraw = *(const ulonglong2*)(wb);
    #pragma unroll 2
    for (int kl = 0; kl < KSL; kl++){
        int kn = (kl + 1 < KSL) ? kl + 1 : kl;
        ulonglong2 wraw2 = *(const ulonglong2*)(wb + (size_t)kn*4096);
        const __half2* hp = (const __half2*)&wraw;
        u64 wv0 = h2u(hp[0]), wv1 = h2u(hp[1]), wv2 = h2u(hp[2]), wv3 = h2u(hp[3]);
        const float* xr = xb + kl*96;
        ulonglong2 xA = *(const ulonglong2*)(xr);
        ulonglong2 xB = *(const ulonglong2*)(xr + 4);
        ulonglong2 xC = *(const ulonglong2*)(xr + 8);
        ulonglong2 xD = *(const ulonglong2*)(xr + 12);
        u64 xv[8] = {xA.x, xA.y, xB.x, xB.y, xC.x, xC.y, xD.x, xD.y};
        #pragma unroll
        for (int j = 0; j < 8; j++){
            acc[j]      = ffma2(wv0, xv[j], acc[j]);
            acc[8 + j]  = ffma2(wv1, xv[j], acc[8 + j]);
            acc[16 + j] = ffma2(wv2, xv[j], acc[16 + j]);
            acc[24 + j] = ffma2(wv3, xv[j], acc[24 + j]);
        }
        wraw = wraw2;
    }
}

// in-block 4-way k-reduce via smem, coalesced global write of 8-ks partials
__device__ __forceinline__ void gemm_reduce_write(float* __restrict__ sh, u64 acc[32],
        float* __restrict__ gpart, int ngrp, int ksM, int wid, int lane)
{
    __syncthreads();                       // xs fully consumed
    {
        float* rp = sh + wid*2176 + lane*68;
        #pragma unroll
        for (int j = 0; j < 8; j++){
            #pragma unroll
            for (int np = 0; np < 4; np++)
                *(u64*)(rp + j*8 + np*2) = acc[np*8 + j];
        }
    }
    __syncthreads();
    if (wid < 4){
        int nt = ngrp*4 + wid;
        float* outp = gpart + (((size_t)ksM*64 + nt)*32)*64;
        int ngr = lane >> 2, npr = lane & 3;
        for (int b = 0; b < 32; b++){
            int bg = b >> 3, j = b & 7;
            float2 s = make_float2(0.f, 0.f);
            #pragma unroll
            for (int r = 0; r < 4; r++){
                float2 v = *(float2*)(sh + (wid + r*4)*2176 + (ngr*4 + bg)*68 + j*8 + npr*2);
                s.x += v.x; s.y += v.y;
            }
            *(float2*)(outp + b*64 + lane*2) = s;
        }
    }
}

// sum the 8 k-split partials for output row n, batch b
__device__ __forceinline__ float part_sum(const float* __restrict__ gpart, int n, int b){
    int ntile = n >> 6, nin = n & 63;
    const float* p = gpart + ((size_t)ntile*32 + b)*64 + nin;
    float s = 0.f;
    #pragma unroll
    for (int ks = 0; ks < 8; ks++) s += p[(size_t)ks*131072];
    return s;
}

// ---------------- output projection (coalesced via dhB/ctxB) ----------------
__device__ __forceinline__ void proj_warps(int nwarp, int lw, int lane, int step,
        const float* __restrict__ pw, const float* __restrict__ pb, float* __restrict__ out){
    for (int o = lw; o < 2560; o += nwarp){
        int mrow = o >> 5, b = o & 31;
        float s = 0.f;
        const float4* w4 = (const float4*)(pw + (size_t)mrow*1536);
        const float4* h4 = (const float4*)(g_dhB + b*1024);
        #pragma unroll
        for (int it = 0; it < 8; it++){
            int j4 = it*32 + lane;
            float4 w = __ldg(&w4[j4]);
            float4 h = h4[j4];
            s += w.x*h.x + w.y*h.y + w.z*h.z + w.w*h.w;
        }
        const float4* c4 = (const float4*)(g_ctxB + b*512);
        #pragma unroll
        for (int it = 0; it < 4; it++){
            int j4 = it*32 + lane;
            float4 w = __ldg(&w4[256 + j4]);
            float4 c = c4[j4];
            s += w.x*c.x + w.y*c.y + w.z*c.z + w.w*c.w;
        }
        #pragma unroll
        for (int off = 16; off; off >>= 1) s += __shfl_down_sync(0xffffffffu, s, off);
        if (lane == 0) __stcs(&out[((size_t)b*512 + step)*80 + mrow], s + __ldg(pb + mrow));
    }
}

// ---------------- persistent decoder ----------------
__global__ void __launch_bounds__(NT, 1) k_persist(
    const float* __restrict__ Ww,
    const float* __restrict__ abih, const float* __restrict__ abhh,
    const float* __restrict__ dbih, const float* __restrict__ dbhh,
    const float* __restrict__ pw,   const float* __restrict__ pb,
    float* __restrict__ out)
{
    extern __shared__ float sh[];
    __shared__ float swg[128];
    const int tid  = threadIdx.x;
    const int bx   = blockIdx.x;
    const int gtid = bx*NT + tid;
    const int lane = tid & 31;
    const int wid  = tid >> 5;

    for (int i = gtid; i < 32768; i += GT){ g_ahT[i]=0.f; g_acT[i]=0.f; g_dhT[i]=0.f; g_dcT[i]=0.f; g_dhB[i]=0.f; }
    for (int i = gtid; i < 16384; i += GT){ g_ctxT[i]=0.f; g_ctxB[i]=0.f; g_aw[i]=0.f; g_aws[i]=0.f; }
    gridbar();

    for (int step = 0; step < 512; step++){
        // ==== P1: attn GEMM (0..127) | dec cell(step-1) (128..147) ====
        if (bx < 128){
            const int KSL = 56, KSB = 224;
            int ngrp = bx >> 3, ksM = bx & 7;
            int k0b = ksM*KSB;
            for (int idx = tid; idx < KSB*32; idx += NT){
                int kl = idx >> 5, b = idx & 31, gk = k0b + kl;
                float v;
                if (gk < 256)      v = __ldcs(&g_pre2T[((size_t)step*256 + gk)*32 + b]);
                else if (gk < 768) v = g_ctxT[(gk-256)*32 + b];
                else               v = g_ahT[(gk-768)*32 + b];
                *(float2*)(sh + kl*96 + (b>>3)*24 + (b&7)*2) = make_float2(v, v);
            }
            __syncthreads();
            int ntile = ngrp*4 + (wid & 3);
            int ksub = wid >> 2;
            u64 acc[32];
            gemm_core(acc, g_WTa, sh + ksub*KSL*96, k0b + ksub*KSL, ntile, lane, KSL);
            gemm_reduce_write(sh, acc, g_partA2, ngrp, ksM, wid, lane);
        } else if (step > 0){
            for (int o = (bx-128)*NT + tid; o < 32768; o += 20*NT){
                int b = o >> 10, j = o & 1023;
                float gi = dbih[j]      + dbhh[j]      + part_sum(g_partD2, j, b);
                float gf = dbih[1024+j] + dbhh[1024+j] + part_sum(g_partD2, 1024+j, b);
                float gg = dbih[2048+j] + dbhh[2048+j] + part_sum(g_partD2, 2048+j, b);
                float go = dbih[3072+j] + dbhh[3072+j] + part_sum(g_partD2, 3072+j, b);
                float c  = g_dcT[j*32+b];
                float c2 = sig_(gf)*c + sig_(gi)*tanh_(gg);
                float h  = sig_(go)*tanh_(c2);
                g_dcT[j*32+b] = c2;
                g_dhT[j*32+b] = h;
                g_dhB[b*1024+j] = h;
            }
        }
        gridbar();

        // ==== P2: attn cell + q partials (0..63) | proj(step-1) (64..147) ====
        if (bx < 64){
            int b = bx >> 1, jhalf = bx & 1;
            int j = (jhalf << 9) + tid;
            float gi = abih[j]      + abhh[j]      + part_sum(g_partA2, j, b);
            float gf = abih[1024+j] + abhh[1024+j] + part_sum(g_partA2, 1024+j, b);
            float gg = abih[2048+j] + abhh[2048+j] + part_sum(g_partA2, 2048+j, b);
            float go = abih[3072+j] + abhh[3072+j] + part_sum(g_partA2, 3072+j, b);
            float c  = g_acT[j*32+b];
            float c2 = sig_(gf)*c + sig_(gi)*tanh_(gg);
            float h  = sig_(go)*tanh_(c2);
            g_acT[j*32+b] = c2;
            g_ahT[j*32+b] = h;
            sh[tid] = h;
            __syncthreads();
            int d = tid & 127, quarter = tid >> 7;
            const float* qt = g_QwT + ((size_t)(jhalf*512 + quarter*128))*128 + d;
            const float* hp = sh + quarter*128;
            float s = 0.f;
            #pragma unroll 8
            for (int jj = 0; jj < 128; jj++) s += qt[(size_t)jj*128] * hp[jj];
            g_qP2[(b*8 + jhalf*4 + quarter)*128 + d] = s;
        } else if (step > 0){
            int lw = (bx - 64)*16 + wid;   // 0..1343
            proj_warps(1344, lw, lane, step-1, pw, pb, out);
        }
        gridbar();

        // ==== P3: energies + softmax partials + ctx partials (0..127) ====
        if (bx < 128){
            int b = bx >> 2, tile = bx & 3, t0 = tile*128;
            for (int i = tid; i < 4096; i += NT){
                int d = i >> 5, k = i & 31;
                sh[d*40 + k]        = g_C1[i];
                sh[5120 + d*40 + k] = g_C2[i];
            }
            if (tid < 128){
                float s = 0.f;
                #pragma unroll
                for (int c = 0; c < 8; c++) s += g_qP2[(b*8 + c)*128 + tid];
                sh[10752 + tid] = s;
                sh[10880 + tid] = __ldg(Ww + tid);
            }
            for (int i = tid; i < 158; i += NT){
                int gi = t0 - 15 + i;
                bool ok = (gi >= 0 && gi < 512);
                sh[11008 + i] = ok ? g_aw [b*512 + gi] : 0.f;
                sh[11168 + i] = ok ? g_aws[b*512 + gi] : 0.f;
            }
            __syncthreads();
            int tt = tid >> 2, sub = tid & 3, t = t0 + tt;
            float ar[32], asr[32];
            #pragma unroll
            for (int k = 0; k < 31; k++){ ar[k] = sh[11008 + tt + k]; asr[k] = sh[11168 + tt + k]; }
            ar[31] = 0.f; asr[31] = 0.f;
            const float* pep = g_peT + (size_t)b*65536 + t;
            float e = 0.f;
            #pragma unroll 1
            for (int dd = 0; dd < 32; dd++){
                int d = dd*4 + sub;
                float l = sh[10752 + d] + __ldg(pep + (size_t)d*512);
                const float4* c14 = (const float4*)(sh + d*40);
                const float4* c24 = (const float4*)(sh + 5120 + d*40);
                #pragma unroll
                for (int i = 0; i < 8; i++){
                    float4 w1 = c14[i], w2 = c24[i];
                    l += ar[i*4]*w1.x + ar[i*4+1]*w1.y + ar[i*4+2]*w1.z + ar[i*4+3]*w1.w;
                    l += asr[i*4]*w2.x + asr[i*4+1]*w2.y + asr[i*4+2]*w2.z + asr[i*4+3]*w2.w;
                }
                e += sh[10880 + d]*tanh_(l);
            }
            e += __shfl_xor_sync(0xffffffffu, e, 1);
            e += __shfl_xor_sync(0xffffffffu, e, 2);
            if (sub == 0){ sh[11328 + tt] = e; g_energy[b*512 + t] = e; }
            __syncthreads();
            if (tid < 128) sh[10240 + tid] = sh[11328 + tid];
            __syncthreads();
            if (tid < 64) sh[10240+tid] = fmaxf(sh[10240+tid], sh[10240+tid+64]);
            __syncthreads();
            if (tid < 32){
                float m = fmaxf(sh[10240+tid], sh[10240+tid+32]);
                #pragma unroll
                for (int o = 16; o; o >>= 1) m = fmaxf(m, __shfl_down_sync(0xffffffffu, m, o));
                if (tid == 0) sh[10240] = m;
            }
            __syncthreads();
            float mi = sh[10240];
            __syncthreads();
            if (tid < 128){
                float p = __expf(sh[11328 + tid] - mi);
                sh[11456 + tid] = p;
                sh[11584 + tid] = p;
            }
            __syncthreads();
            if (tid < 64) sh[11584+tid] += sh[11584+tid+64];
            __syncthreads();
            if (tid < 32){
                float s = sh[11584+tid] + sh[11584+tid+32];
                #pragma unroll
                for (int o = 16; o; o >>= 1) s += __shfl_down_sync(0xffffffffu, s, o);
                if (tid == 0){ g_m[tile*32 + b] = mi; g_s[tile*32 + b] = s; }
            }
            __syncthreads();
            // ctx partial from L2-RESIDENT fp16 enc (hot set ~70MB with fp16 weights)
            {
                int th = tid >> 8, p = tid & 255;          // t-half, e-pair
                float2 a2 = make_float2(0.f, 0.f);
                const __half2* ep = g_encH + ((size_t)b*512 + t0 + th*64)*256 + p;
                #pragma unroll 8
                for (int t2 = 0; t2 < 64; t2++){
                    float w = sh[11456 + th*64 + t2];
                    float2 ev = __half22float2(__ldg(&ep[(size_t)t2*256]));
                    a2.x += w*ev.x; a2.y += w*ev.y;
                }
                sh[11712 + th*512 + 2*p]     = a2.x;
                sh[11712 + th*512 + 2*p + 1] = a2.y;
            }
            __syncthreads();
            float acc = sh[11712 + tid] + sh[12224 + tid];
            g_ctxP[((size_t)tile*512 + tid)*32 + b] = acc;
        }
        gridbar();

        // ==== P4: dec GEMM + inline ctx reduce (0..127) | finalize (128..147) ====
        if (bx < 128){
            if (tid < 32){
                int b = tid;
                float m0=g_m[b], m1=g_m[32+b], m2=g_m[64+b], m3=g_m[96+b];
                float M = fmaxf(fmaxf(m0,m1), fmaxf(m2,m3));
                float e0=__expf(m0-M), e1=__expf(m1-M), e2=__expf(m2-M), e3=__expf(m3-M);
                float S = g_s[b]*e0 + g_s[32+b]*e1 + g_s[64+b]*e2 + g_s[96+b]*e3;
                float inv = __fdividef(1.f, S);
                swg[b]=e0*inv; swg[32+b]=e1*inv; swg[64+b]=e2*inv; swg[96+b]=e3*inv;
            }
            __syncthreads();
            const int KSL = 80, KSB = 320;
            int ngrp = bx >> 3, ksM = bx & 7;
            int k0b = ksM*KSB;
            for (int idx = tid; idx < KSB*32; idx += NT){
                int kl = idx >> 5, b = idx & 31, gk = k0b + kl;
                float v;
                if (gk < 1024)      v = g_ahT[gk*32 + b];
                else if (gk < 1536){
                    int o = (gk-1024)*32 + b;
                    v = swg[b]*g_ctxP[o] + swg[32+b]*g_ctxP[16384+o]
                      + swg[64+b]*g_ctxP[32768+o] + swg[96+b]*g_ctxP[49152+o];
                } else               v = g_dhT[(gk-1536)*32 + b];
                *(float2*)(sh + kl*96 + (b>>3)*24 + (b&7)*2) = make_float2(v, v);
            }
            __syncthreads();
            int ntile = ngrp*4 + (wid & 3);
            int ksub = wid >> 2;
            u64 acc[32];
            gemm_core(acc, g_WTd, sh + ksub*KSL*96, k0b + ksub*KSL, ntile, lane, KSL);
            gemm_reduce_write(sh, acc, g_partD2, ngrp, ksM, wid, lane);
        } else {
            for (int b = bx - 128; b < 32; b += 20){
                float m0=g_m[b], m1=g_m[32+b], m2=g_m[64+b], m3=g_m[96+b];
                float M = fmaxf(fmaxf(m0,m1), fmaxf(m2,m3));
                float e0=__expf(m0-M), e1=__expf(m1-M), e2=__expf(m2-M), e3=__expf(m3-M);
                float S = g_s[b]*e0 + g_s[32+b]*e1 + g_s[64+b]*e2 + g_s[96+b]*e3;
                float inv = __fdividef(1.f, S);
                float w0=e0*inv, w1=e1*inv, w2=e2*inv, w3=e3*inv;
                float a = __expf(g_energy[b*512 + tid] - M)*inv;
                g_aw[b*512 + tid] = a;
                g_aws[b*512 + tid] += a;
                __stcs(&out[MEL_TOT + ((size_t)b*512 + step)*512 + tid], a);
                int o = tid*32 + b;
                float v = w0*g_ctxP[o] + w1*g_ctxP[16384+o] + w2*g_ctxP[32768+o] + w3*g_ctxP[49152+o];
                g_ctxT[o] = v;
                g_ctxB[b*512 + tid] = v;
            }
        }
        gridbar();
    }

    // ==== epilogue: dec cell for step 511, then proj(511) ====
    for (int o = gtid; o < 32768; o += GT){
        int b = o >> 10, j = o & 1023;
        float gi = dbih[j]      + dbhh[j]      + part_sum(g_partD2, j, b);
        float gf = dbih[1024+j] + dbhh[1024+j] + part_sum(g_partD2, 1024+j, b);
        float gg = dbih[2048+j] + dbhh[2048+j] + part_sum(g_partD2, 2048+j, b);
        float go = dbih[3072+j] + dbhh[3072+j] + part_sum(g_partD2, 3072+j, b);
        float c  = g_dcT[j*32+b];
        float c2 = sig_(gf)*c + sig_(gi)*tanh_(gg);
        float h  = sig_(go)*tanh_(c2);
        g_dhB[b*1024+j] = h;
    }
    gridbar();
    proj_warps(NB*16, gtid >> 5, lane, 511, pw, pb, out);
}

// ---------------- launch ----------------
extern "C" void kernel_launch(void* const* d_in, const int* in_sizes, int n_in,
                              void* d_out, int out_size){
    const float* enc   = (const float*)d_in[0];
    const float* tgt   = (const float*)d_in[1];
    const float* w1    = (const float*)d_in[2];
    const float* b1    = (const float*)d_in[3];
    const float* w2    = (const float*)d_in[4];
    const float* b2    = (const float*)d_in[5];
    const float* Mw    = (const float*)d_in[6];
    const float* Qw    = (const float*)d_in[7];
    const float* Ww    = (const float*)d_in[8];
    const float* Lw    = (const float*)d_in[9];
    const float* convw = (const float*)d_in[10];
    const float* awih  = (const float*)d_in[11];
    const float* awhh  = (const float*)d_in[12];
    const float* abih  = (const float*)d_in[13];
    const float* abhh  = (const float*)d_in[14];
    const float* dwih  = (const float*)d_in[15];
    const float* dwhh  = (const float*)d_in[16];
    const float* dbih  = (const float*)d_in[17];
    const float* dbhh  = (const float*)d_in[18];
    const float* pw    = (const float*)d_in[19];
    const float* pb    = (const float*)d_in[20];
    float* out = (float*)d_out;

    kprepA<<<22928, 256>>>(tgt, Mw, Lw, convw, awih, awhh, dwih, dwhh, Qw);
    kprepB<<<16384, 256>>>(w1, b1);
    kprepC<<<24576, 256>>>(w2, b2, enc);

    cudaFuncSetAttribute(k_persist, cudaFuncAttributeMaxDynamicSharedMemorySize, 143360);
    k_persist<<<NB, NT, 143360>>>(Ww, abih, abhh, dbih, dbhh, pw, pb, out);
}